// round 4
// baseline (speedup 1.0000x reference)
#include <cuda_runtime.h>

// ---------------------------------------------------------------------------
// Problem constants
// ---------------------------------------------------------------------------
#define NN     2048          // n == nfft (2048 is already a power of two)
#define NSC    81            // number of scales: J=80 -> 81
#define NB     64            // batch pairs
#define TPB    256
#define WSZ    94            // sliding window
#define NOUT   (NN - WSZ + 1)  // 1955

#define S0F        0.1936026618f            // 2*dt*(w0+sqrt(2+w0^2))/(4*pi)
#define WFAC       0.030679615757712823f    // 2*pi / (2048*0.1)
#define KFAC       0.0030679615757712823f   // 2*pi / 2048
#define TWOPI_F    6.283185307179586f
#define INV_PI4    0.7511255444649425f      // pi^(-1/4)

// ---------------------------------------------------------------------------
// Scratch (device globals; no allocation anywhere)
// ---------------------------------------------------------------------------
static __device__ float2 g_Y  [NB * 2 * NN];          // FFT of normalized signals
static __device__ float  g_T1 [(size_t)NB * NSC * NN]; // time-smoothed |W1|^2/s
static __device__ float  g_T2 [(size_t)NB * NSC * NN]; // time-smoothed |W2|^2/s
static __device__ float2 g_T12[(size_t)NB * NSC * NN]; // time-smoothed W1*conj(W2)/s
static __device__ float  g_coh[NB * NN];               // coherence summed over scales

// ---------------------------------------------------------------------------
// Complex helpers
// ---------------------------------------------------------------------------
__device__ __forceinline__ float2 cmul(float2 a, float2 b) {
    return make_float2(a.x * b.x - a.y * b.y, a.x * b.y + a.y * b.x);
}
__device__ __forceinline__ float2 cadd(float2 a, float2 b) { return make_float2(a.x + b.x, a.y + b.y); }
__device__ __forceinline__ float2 csub(float2 a, float2 b) { return make_float2(a.x - b.x, a.y - b.y); }

// Twiddle table: tw[k] = exp(-i*2*pi*k/2048), k in [0,1024)
__device__ __forceinline__ void fill_tw(float2* tw, int tid) {
    #pragma unroll
    for (int k = tid; k < 1024; k += TPB) {
        float s, c;
        sincospif(-(float)k * (1.0f / 1024.0f), &s, &c);
        tw[k] = make_float2(c, s);
    }
}

template <bool INV>
__device__ __forceinline__ float2 twget(const float2* tw, int k) {
    float2 w = tw[k];
    if (INV) w.y = -w.y;
    return w;
}

// ---------------------------------------------------------------------------
// Mixed-radix Stockham FFT, N = 2048 = 4^5 * 2, natural order in & out.
// Unscaled (no 1/N on inverse) — callers fold the scaling into pointwise ops.
// ---------------------------------------------------------------------------
template <int NSv, bool INV>
__device__ __forceinline__ void r4_stage(const float2* __restrict__ src,
                                         float2* __restrict__ dst,
                                         const float2* __restrict__ tw, int tid) {
    const int STEP = 512 / NSv;
    #pragma unroll
    for (int j = tid; j < 512; j += TPB) {
        int p = j & (NSv - 1);
        int q = j / NSv;
        float2 v0 = src[j];
        float2 v1 = src[j + 512];
        float2 v2 = src[j + 1024];
        float2 v3 = src[j + 1536];
        if (NSv > 1) {
            float2 w1 = twget<INV>(tw, p * STEP);
            float2 w2 = cmul(w1, w1);
            float2 w3 = cmul(w2, w1);
            v1 = cmul(v1, w1);
            v2 = cmul(v2, w2);
            v3 = cmul(v3, w3);
        }
        float2 a = cadd(v0, v2), b = csub(v0, v2);
        float2 c = cadd(v1, v3), d = csub(v1, v3);
        // forward: -i*d ; inverse: +i*d
        float2 di = INV ? make_float2(-d.y, d.x) : make_float2(d.y, -d.x);
        int o = q * (4 * NSv) + p;
        dst[o]           = cadd(a, c);
        dst[o + NSv]     = cadd(b, di);
        dst[o + 2 * NSv] = csub(a, c);
        dst[o + 3 * NSv] = csub(b, di);
    }
}

template <bool INV>
__device__ __forceinline__ void r2_stage(const float2* __restrict__ src,
                                         float2* __restrict__ dst,
                                         const float2* __restrict__ tw, int tid) {
    #pragma unroll
    for (int j = tid; j < 1024; j += TPB) {
        float2 v0 = src[j];
        float2 v1 = src[j + 1024];
        float2 w = twget<INV>(tw, j);
        v1 = cmul(v1, w);
        dst[j]        = cadd(v0, v1);
        dst[j + 1024] = csub(v0, v1);
    }
}

template <bool INV>
__device__ __noinline__ void fft2048(float2* A, float2* Bf, const float2* tw, int tid) {
    __syncthreads();
    r4_stage<1,   INV>(A,  Bf, tw, tid); __syncthreads();
    r4_stage<4,   INV>(Bf, A,  tw, tid); __syncthreads();
    r4_stage<16,  INV>(A,  Bf, tw, tid); __syncthreads();
    r4_stage<64,  INV>(Bf, A,  tw, tid); __syncthreads();
    r4_stage<256, INV>(A,  Bf, tw, tid); __syncthreads();
    r2_stage<INV>(Bf, A, tw, tid);       __syncthreads();
}

// ---------------------------------------------------------------------------
// Block reduction (256 threads)
// ---------------------------------------------------------------------------
__device__ __forceinline__ float block_reduce(float v, float* red) {
    int tid = threadIdx.x;
    #pragma unroll
    for (int o = 16; o > 0; o >>= 1) v += __shfl_xor_sync(0xffffffffu, v, o);
    if ((tid & 31) == 0) red[tid >> 5] = v;
    __syncthreads();
    if (tid < 32) {
        float r = (tid < TPB / 32) ? red[tid] : 0.f;
        #pragma unroll
        for (int o = 4; o > 0; o >>= 1) r += __shfl_xor_sync(0xffffffffu, r, o);
        if (tid == 0) red[32] = r;
    }
    __syncthreads();
    float r = red[32];
    __syncthreads();   // protect red for reuse
    return r;
}

// ---------------------------------------------------------------------------
// K0: normalize each signal and take its forward FFT -> g_Y
// grid = 128 (64 pairs * 2 signals)
// ---------------------------------------------------------------------------
__global__ void __launch_bounds__(TPB) k0_normfft(const float* __restrict__ x) {
    __shared__ float2 A[NN], Bf[NN], tw[1024];
    __shared__ float red[33];
    int b = blockIdx.x;
    int tid = threadIdx.x;
    const float* y = x + (size_t)b * NN;

    fill_tw(tw, tid);

    float s = 0.f;
    #pragma unroll
    for (int i = tid; i < NN; i += TPB) s += y[i];
    float mean = block_reduce(s, red) * (1.0f / NN);

    float v = 0.f;
    #pragma unroll
    for (int i = tid; i < NN; i += TPB) { float d = y[i] - mean; v += d * d; }
    float var = block_reduce(v, red) * (1.0f / NN);
    float istd = rsqrtf(var);

    #pragma unroll
    for (int i = tid; i < NN; i += TPB)
        A[i] = make_float2((y[i] - mean) * istd, 0.f);

    fft2048<false>(A, Bf, tw, tid);

    float2* out = g_Y + (size_t)b * NN;
    #pragma unroll
    for (int i = tid; i < NN; i += TPB) out[i] = A[i];
}

// ---------------------------------------------------------------------------
// K1: per (pair, scale): CWT of both signals, power/cross terms, Gaussian
// time smoothing in Fourier domain -> g_T1, g_T2, g_T12
// grid = 64*81 = 5184, dynamic smem = (3*2048 + 1024) float2 = 57344 B
// ---------------------------------------------------------------------------
extern __shared__ float2 sm1[];
__global__ void __launch_bounds__(TPB) k1_scale() {
    float2* A  = sm1;
    float2* Bf = A + NN;
    float2* X  = Bf + NN;     // holds W1, then C
    float2* tw = X + NN;      // 1024 entries
    int blk  = blockIdx.x;
    int pair = blk / NSC;
    int js   = blk - pair * NSC;
    int tid  = threadIdx.x;

    fill_tw(tw, tid);

    float sc  = S0F * exp2f(0.125f * (float)js);
    float nrm = sqrtf(TWOPI_F * sc * 10.0f) * INV_PI4;   // sqrt(2*pi*s/dt) * pi^-1/4

    const float2* Y1 = g_Y + (size_t)pair * 2 * NN;
    const float2* Y2 = Y1 + NN;

    // ---- W1 = unscaled ifft(Y1 * H) ----
    #pragma unroll
    for (int i = tid; i < NN; i += TPB) {
        float h = 0.f;
        if (i >= 1 && i <= 1023) {
            float t = sc * (WFAC * (float)i) - 6.0f;
            h = nrm * expf(-0.5f * t * t);
        }
        float2 yv = Y1[i];
        A[i] = make_float2(yv.x * h, yv.y * h);
    }
    fft2048<true>(A, Bf, tw, tid);

    // stash W1, set up W2 input
    #pragma unroll
    for (int i = tid; i < NN; i += TPB) {
        X[i] = A[i];
        float h = 0.f;
        if (i >= 1 && i <= 1023) {
            float t = sc * (WFAC * (float)i) - 6.0f;
            h = nrm * expf(-0.5f * t * t);
        }
        float2 yv = Y2[i];
        A[i] = make_float2(yv.x * h, yv.y * h);
    }
    fft2048<true>(A, Bf, tw, tid);   // A = W2 (unscaled)

    // ---- pointwise: P = (|W1|^2 + i|W2|^2)/s, C = W1*conj(W2)/s ----
    const float scf = (1.0f / sc) * (1.0f / ((float)NN * (float)NN)); // fold 2x 1/N
    #pragma unroll
    for (int i = tid; i < NN; i += TPB) {
        float2 w1 = X[i], w2 = A[i];
        float p1 = (w1.x * w1.x + w1.y * w1.y) * scf;
        float p2 = (w2.x * w2.x + w2.y * w2.y) * scf;
        X[i] = make_float2((w1.x * w2.x + w1.y * w2.y) * scf,
                           (w1.y * w2.x - w1.x * w2.y) * scf);
        A[i] = make_float2(p1, p2);
    }

    // ---- time smoothing of P (packed pair) ----
    fft2048<false>(A, Bf, tw, tid);
    float sd = sc * 10.0f;            // s/dt
    float a2 = sd * sd;
    const float invN = 1.0f / (float)NN;
    #pragma unroll
    for (int i = tid; i < NN; i += TPB) {
        int m = (i < 1024) ? i : (NN - i);
        float k = KFAC * (float)m;
        float g = expf(-0.5f * a2 * k * k) * invN;
        A[i].x *= g;
        A[i].y *= g;
    }
    fft2048<true>(A, Bf, tw, tid);    // A = T1 + i*T2

    size_t base = ((size_t)pair * NSC + js) * NN;
    #pragma unroll
    for (int i = tid; i < NN; i += TPB) {
        float2 t = A[i];
        g_T1[base + i] = t.x;
        g_T2[base + i] = t.y;
        A[i] = X[i];                  // load C for its smoothing pass
    }

    // ---- time smoothing of C ----
    fft2048<false>(A, Bf, tw, tid);
    #pragma unroll
    for (int i = tid; i < NN; i += TPB) {
        int m = (i < 1024) ? i : (NN - i);
        float k = KFAC * (float)m;
        float g = expf(-0.5f * a2 * k * k) * invN;
        A[i].x *= g;
        A[i].y *= g;
    }
    fft2048<true>(A, Bf, tw, tid);    // A = T12

    #pragma unroll
    for (int i = tid; i < NN; i += TPB) g_T12[base + i] = A[i];
}

// ---------------------------------------------------------------------------
// K2: scale smoothing (10-tap, half-weight ends) + coherence + sum over scales.
// The 1/9 window normalization cancels in |S12|^2/(S1*S2).
// grid = 64 pairs * 64 tiles of 32 time samples
// ---------------------------------------------------------------------------
__global__ void __launch_bounds__(TPB) k2_coh() {
    __shared__ float s1[NSC * 32], s2[NSC * 32], cr[NSC * 32], ci[NSC * 32];
    __shared__ float scoh[32];
    int blk  = blockIdx.x;
    int pair = blk >> 6;
    int t0   = (blk & 63) * 32;
    int tid  = threadIdx.x;

    size_t base = (size_t)pair * NSC * NN + t0;
    for (int idx = tid; idx < NSC * 32; idx += TPB) {
        int row = idx >> 5, col = idx & 31;
        size_t g = base + (size_t)row * NN + col;
        s1[idx] = g_T1[g];
        s2[idx] = g_T2[g];
        float2 c = g_T12[g];
        cr[idx] = c.x;
        ci[idx] = c.y;
    }
    if (tid < 32) scoh[tid] = 0.f;
    __syncthreads();

    int tl = tid & 31, jg = tid >> 5;   // 8 scale-groups x 32 time lanes
    float acc = 0.f;
    for (int j = jg; j < NSC; j += 8) {
        float a = 0.f, b = 0.f, c = 0.f, d = 0.f;
        #pragma unroll
        for (int k = 0; k < 10; k++) {
            int r = j + 4 - k;          // np.convolve 'same', length-10 kernel
            if (r >= 0 && r < NSC) {
                float w = (k == 0 || k == 9) ? 0.5f : 1.0f;
                int ix = r * 32 + tl;
                a += w * s1[ix];
                b += w * s2[ix];
                c += w * cr[ix];
                d += w * ci[ix];
            }
        }
        acc += (c * c + d * d) / (a * b);
    }
    atomicAdd(&scoh[tl], acc);
    __syncthreads();
    if (tid < 32) g_coh[(size_t)pair * NN + t0 + tid] = scoh[tid];
}

// ---------------------------------------------------------------------------
// K3: sliding-window sum (window 94) -> out [64, 1955]
// ---------------------------------------------------------------------------
__global__ void __launch_bounds__(TPB) k3_window(float* __restrict__ out) {
    __shared__ float c[NN];
    int pair = blockIdx.x;
    int tid  = threadIdx.x;
    for (int i = tid; i < NN; i += TPB) c[i] = g_coh[(size_t)pair * NN + i];
    __syncthreads();
    for (int t = tid; t < NOUT; t += TPB) {
        float s = 0.f;
        for (int k = 0; k < WSZ; k++) s += c[t + k];
        out[(size_t)pair * NOUT + t] = s;
    }
}

// ---------------------------------------------------------------------------
// Entry point
// ---------------------------------------------------------------------------
extern "C" void kernel_launch(void* const* d_in, const int* in_sizes, int n_in,
                              void* d_out, int out_size) {
    (void)in_sizes; (void)n_in; (void)out_size;
    const float* x = (const float*)d_in[0];
    float* out = (float*)d_out;

    // 3 ping-pong/stash buffers + twiddle table: (3*2048 + 1024) * 8 B = 57344 B
    cudaFuncSetAttribute(k1_scale, cudaFuncAttributeMaxDynamicSharedMemorySize, 57344);

    k0_normfft<<<NB * 2, TPB>>>(x);
    k1_scale<<<NB * NSC, TPB, 57344>>>();
    k2_coh<<<NB * 64, TPB>>>();
    k3_window<<<NB, TPB>>>(out);
}

// round 5
// speedup vs baseline: 1.4172x; 1.4172x over previous
#include <cuda_runtime.h>

// ---------------------------------------------------------------------------
// Problem constants
// ---------------------------------------------------------------------------
#define NN     2048
#define NSC    81
#define NB     64
#define TPB    256
#define WSZ    94
#define NOUT   (NN - WSZ + 1)  // 1955

#define S0F        0.1936026618f            // 2*dt*(w0+sqrt(2+w0^2))/(4*pi)
#define WFAC       0.030679615757712823f    // 2*pi / (2048*0.1)
#define KFAC       0.0030679615757712823f   // 2*pi / 2048
#define TWOPI_F    6.283185307179586f
#define INV_PI4    0.7511255444649425f      // pi^(-1/4)

// ---------------------------------------------------------------------------
// Scratch (device globals; no allocation anywhere)
// ---------------------------------------------------------------------------
static __device__ float2 g_Y  [NB * 2 * NN];
static __device__ float  g_T1 [(size_t)NB * NSC * NN];
static __device__ float  g_T2 [(size_t)NB * NSC * NN];
static __device__ float2 g_T12[(size_t)NB * NSC * NN];
static __device__ float  g_coh[NB * NN];

// ---------------------------------------------------------------------------
// Complex helpers
// ---------------------------------------------------------------------------
__device__ __forceinline__ float2 cmul(float2 a, float2 b) {
    return make_float2(a.x * b.x - a.y * b.y, a.x * b.y + a.y * b.x);
}
__device__ __forceinline__ float2 cadd(float2 a, float2 b) { return make_float2(a.x + b.x, a.y + b.y); }
__device__ __forceinline__ float2 csub(float2 a, float2 b) { return make_float2(a.x - b.x, a.y - b.y); }

// ---------------------------------------------------------------------------
// Bank swizzle: s(i) = i ^ g(i>>4), g(h) = (h&7) ^ ((h&4)<<1).
// Makes all Stockham read/write patterns below conflict-free per half-warp.
// ---------------------------------------------------------------------------
__device__ __forceinline__ int gmask(int h) { return (h & 7) ^ ((h & 4) << 1); }
__device__ __forceinline__ int sw(int i)    { return i ^ gmask(i >> 4); }

// ---------------------------------------------------------------------------
// Radix-8 butterfly. Input v[0..7] (twiddles already applied); output in place:
// v[r] = sum_m v_m * w8^{r*m}, w8 = exp(-2*pi*i/8) fwd, conj for INV.
// ---------------------------------------------------------------------------
template <bool INV>
__device__ __forceinline__ float2 mulmi(float2 z) {   // *(-i) fwd, *(+i) inv
    return INV ? make_float2(-z.y, z.x) : make_float2(z.y, -z.x);
}

template <bool INV>
__device__ __forceinline__ void bf8_tail(float2 E0, float2 E1, float2 E2, float2 E3,
                                         float2 O0, float2 O1, float2 O2, float2 O3,
                                         float2 v[8]) {
    const float RS = 0.70710678118654752f;
    float2 W1, W3;
    if (!INV) {
        W1 = make_float2(RS * (O1.x + O1.y), RS * (O1.y - O1.x));   // e^{-i pi/4}  * O1
        W3 = make_float2(RS * (O3.y - O3.x), -RS * (O3.x + O3.y));  // e^{-3i pi/4} * O3
    } else {
        W1 = make_float2(RS * (O1.x - O1.y), RS * (O1.x + O1.y));   // e^{+i pi/4}
        W3 = make_float2(-RS * (O3.x + O3.y), RS * (O3.x - O3.y));  // e^{+3i pi/4}
    }
    float2 O2i = mulmi<INV>(O2);
    v[0] = cadd(E0, O0);  v[4] = csub(E0, O0);
    v[1] = cadd(E1, W1);  v[5] = csub(E1, W1);
    v[2] = cadd(E2, O2i); v[6] = csub(E2, O2i);
    v[3] = cadd(E3, W3);  v[7] = csub(E3, W3);
}

template <bool INV>
__device__ __forceinline__ void bf8(float2 v[8]) {
    float2 e0 = cadd(v[0], v[4]), e1 = csub(v[0], v[4]);
    float2 e2 = cadd(v[2], v[6]), e3 = csub(v[2], v[6]);
    float2 e3i = mulmi<INV>(e3);
    float2 E0 = cadd(e0, e2), E1 = cadd(e1, e3i), E2 = csub(e0, e2), E3 = csub(e1, e3i);
    float2 o0 = cadd(v[1], v[5]), o1 = csub(v[1], v[5]);
    float2 o2 = cadd(v[3], v[7]), o3 = csub(v[3], v[7]);
    float2 o3i = mulmi<INV>(o3);
    float2 O0 = cadd(o0, o2), O1 = cadd(o1, o3i), O2 = csub(o0, o2), O3 = csub(o1, o3i);
    bf8_tail<INV>(E0, E1, E2, E3, O0, O1, O2, O3, v);
}

// Half-input butterfly: v[0..3] valid, v[4..7] == 0 (Morlet filter support).
template <bool INV>
__device__ __forceinline__ void bf8h(float2 v[8]) {
    float2 a0 = v[0], a1 = v[2], b0 = v[1], b1 = v[3];
    float2 a1i = mulmi<INV>(a1);
    float2 E0 = cadd(a0, a1), E1 = cadd(a0, a1i), E2 = csub(a0, a1), E3 = csub(a0, a1i);
    float2 b1i = mulmi<INV>(b1);
    float2 O0 = cadd(b0, b1), O1 = cadd(b0, b1i), O2 = csub(b0, b1), O3 = csub(b0, b1i);
    bf8_tail<INV>(E0, E1, E2, E3, O0, O1, O2, O3, v);
}

// Twiddle chain: w[m] = exp(-+ i*pi*x*m)  (forward: -, inverse: +)
template <bool INV>
__device__ __forceinline__ void tw_chain(float x, float2 w[8]) {
    float s_, c_;
    sincospif(INV ? x : -x, &s_, &c_);
    w[1] = make_float2(c_, s_);
    w[2] = cmul(w[1], w[1]);
    w[3] = cmul(w[2], w[1]);
    w[4] = cmul(w[2], w[2]);
    w[5] = cmul(w[3], w[2]);
    w[6] = cmul(w[3], w[3]);
    w[7] = cmul(w[4], w[3]);
}

// ---------------------------------------------------------------------------
// Stockham passes, N = 2048 = 8*8*8*4, 256 threads, in-place single buffer.
// NSv sequence 1 -> 8 -> 64 -> 512 -> 2048.
// Data stored at swizzled indices throughout; logical index k lives at sw(k).
// ---------------------------------------------------------------------------
template <bool INV, bool HALF>
__device__ __forceinline__ void pass1(float2* A, float2 v[8], int t) {
    __syncthreads();           // A's previous readers are done
    if (HALF) bf8h<INV>(v); else bf8<INV>(v);
    int mw = gmask(t >> 1);
    int b8 = 8 * t;
    #pragma unroll
    for (int r = 0; r < 8; r++) A[(b8 + r) ^ mw] = v[r];
    __syncthreads();
}

template <bool INV>
__device__ __forceinline__ void pass2(float2* A, int t) {
    float2 v[8];
    int mr = gmask(t >> 4);
    #pragma unroll
    for (int m = 0; m < 8; m++) v[m] = A[(t + 256 * m) ^ mr];
    __syncthreads();
    int p = t & 7;
    float2 w[8];
    tw_chain<INV>((float)p * (1.0f / 32.0f), w);
    #pragma unroll
    for (int m = 1; m < 8; m++) v[m] = cmul(v[m], w[m]);
    bf8<INV>(v);
    int o = (t >> 3) * 64 + p;
    #pragma unroll
    for (int r = 0; r < 8; r++) { int i = o + 8 * r; A[sw(i)] = v[r]; }
    __syncthreads();
}

template <bool INV>
__device__ __forceinline__ void pass3(float2* A, int t) {
    float2 v[8];
    int mr = gmask(t >> 4);
    #pragma unroll
    for (int m = 0; m < 8; m++) v[m] = A[(t + 256 * m) ^ mr];
    __syncthreads();
    int p = t & 63;
    float2 w[8];
    tw_chain<INV>((float)p * (1.0f / 256.0f), w);
    #pragma unroll
    for (int m = 1; m < 8; m++) v[m] = cmul(v[m], w[m]);
    bf8<INV>(v);
    int o = (t >> 6) * 512 + p;
    #pragma unroll
    for (int r = 0; r < 8; r++) { int i = o + 64 * r; A[sw(i)] = v[r]; }
    __syncthreads();
}

// Final radix-4 pass (NSv=512). Computes both butterflies, then stores.
template <bool INV>
__device__ __forceinline__ void pass4_core(const float2* A, int t, float2 u[2][4]) {
    #pragma unroll
    for (int b = 0; b < 2; b++) {
        int j = t + 256 * b;
        int mr = gmask(j >> 4);
        float2 v0 = A[j ^ mr];
        float2 v1 = A[(j + 512) ^ mr];
        float2 v2 = A[(j + 1024) ^ mr];
        float2 v3 = A[(j + 1536) ^ mr];
        float s_, c_;
        float a = (float)j * (1.0f / 1024.0f);
        sincospif(INV ? a : -a, &s_, &c_);
        float2 w1 = make_float2(c_, s_);
        float2 w2 = cmul(w1, w1);
        float2 w3 = cmul(w2, w1);
        v1 = cmul(v1, w1); v2 = cmul(v2, w2); v3 = cmul(v3, w3);
        float2 aa = cadd(v0, v2), bb = csub(v0, v2);
        float2 cc = cadd(v1, v3), dd = csub(v1, v3);
        float2 di = mulmi<INV>(dd);
        u[b][0] = cadd(aa, cc); u[b][1] = cadd(bb, di);
        u[b][2] = csub(aa, cc); u[b][3] = csub(bb, di);
    }
}

template <bool INV>
__device__ __forceinline__ void pass4(const float2* A, float2* D, int t) {
    float2 u[2][4];
    pass4_core<INV>(A, t, u);
    __syncthreads();
    #pragma unroll
    for (int b = 0; b < 2; b++) {
        int j = t + 256 * b;
        int mw = gmask(j >> 4);
        #pragma unroll
        for (int r = 0; r < 4; r++) D[(j + 512 * r) ^ mw] = u[b][r];
    }
    __syncthreads();
}

// Final pass writing T1/T2 (re/im) straight to global (coalesced).
template <bool INV>
__device__ __forceinline__ void pass4_gT(const float2* A, float* T1, float* T2, int t) {
    float2 u[2][4];
    pass4_core<INV>(A, t, u);
    #pragma unroll
    for (int b = 0; b < 2; b++) {
        int j = t + 256 * b;
        #pragma unroll
        for (int r = 0; r < 4; r++) { T1[j + 512 * r] = u[b][r].x; T2[j + 512 * r] = u[b][r].y; }
    }
    // no sync: next pass1 starts with one
}

template <bool INV>
__device__ __forceinline__ void pass4_gC(const float2* A, float2* T12, int t) {
    float2 u[2][4];
    pass4_core<INV>(A, t, u);
    #pragma unroll
    for (int b = 0; b < 2; b++) {
        int j = t + 256 * b;
        #pragma unroll
        for (int r = 0; r < 4; r++) T12[j + 512 * r] = u[b][r];
    }
}

// ---------------------------------------------------------------------------
// Block reduction (256 threads)
// ---------------------------------------------------------------------------
__device__ __forceinline__ float block_reduce(float v, float* red) {
    int tid = threadIdx.x;
    #pragma unroll
    for (int o = 16; o > 0; o >>= 1) v += __shfl_xor_sync(0xffffffffu, v, o);
    if ((tid & 31) == 0) red[tid >> 5] = v;
    __syncthreads();
    if (tid < 32) {
        float r = (tid < TPB / 32) ? red[tid] : 0.f;
        #pragma unroll
        for (int o = 4; o > 0; o >>= 1) r += __shfl_xor_sync(0xffffffffu, r, o);
        if (tid == 0) red[32] = r;
    }
    __syncthreads();
    float r = red[32];
    __syncthreads();
    return r;
}

// ---------------------------------------------------------------------------
// K0: normalize each signal + forward FFT -> g_Y.  grid = 128
// ---------------------------------------------------------------------------
__global__ void __launch_bounds__(TPB) k0_normfft(const float* __restrict__ x) {
    __shared__ float2 A[NN];
    __shared__ float red[33];
    int b = blockIdx.x, t = threadIdx.x;
    const float* y = x + (size_t)b * NN;

    float s = 0.f;
    #pragma unroll
    for (int i = t; i < NN; i += TPB) s += y[i];
    float mean = block_reduce(s, red) * (1.0f / NN);

    float vv = 0.f;
    #pragma unroll
    for (int i = t; i < NN; i += TPB) { float d = y[i] - mean; vv += d * d; }
    float istd = rsqrtf(block_reduce(vv, red) * (1.0f / NN));

    float2 v[8];
    #pragma unroll
    for (int m = 0; m < 8; m++) {
        int i = t + 256 * m;
        v[m] = make_float2((y[i] - mean) * istd, 0.f);
    }
    pass1<false, false>(A, v, t);
    pass2<false>(A, t);
    pass3<false>(A, t);
    pass4<false>(A, A, t);

    int mr = gmask(t >> 4);
    float2* out = g_Y + (size_t)b * NN;
    #pragma unroll
    for (int m = 0; m < 8; m++) { int i = t + 256 * m; out[i] = A[i ^ mr]; }
}

// ---------------------------------------------------------------------------
// K1: per (pair, scale) full chain with fused pointwise ops. grid = 5184
// ---------------------------------------------------------------------------
__global__ void __launch_bounds__(TPB, 4) k1_scale() {
    __shared__ float2 A[NN];
    __shared__ float2 X[NN];
    int blk = blockIdx.x;
    int pair = blk / NSC;
    int js = blk - pair * NSC;
    int t = threadIdx.x;

    float sc  = S0F * exp2f(0.125f * (float)js);
    float nrm = sqrtf(TWOPI_F * sc * 10.0f) * INV_PI4;
    const float2* Y1 = g_Y + (size_t)pair * 2 * NN;
    const float2* Y2 = Y1 + NN;
    int mr = gmask(t >> 4);

    float2 v[8];

    // ---- FFT1: W1 = unscaled ifft(Y1*H)  (H zero for bins >= 1024) -> X ----
    #pragma unroll
    for (int m = 0; m < 4; m++) {
        int i = t + 256 * m;
        float tt = sc * (WFAC * (float)i) - 6.0f;
        float h = (i >= 1) ? nrm * expf(-0.5f * tt * tt) : 0.f;
        float2 yv = Y1[i];
        v[m] = make_float2(yv.x * h, yv.y * h);
    }
    pass1<true, true>(A, v, t);
    pass2<true>(A, t);
    pass3<true>(A, t);
    pass4<true>(A, X, t);

    // ---- FFT2: W2 -> A ----
    #pragma unroll
    for (int m = 0; m < 4; m++) {
        int i = t + 256 * m;
        float tt = sc * (WFAC * (float)i) - 6.0f;
        float h = (i >= 1) ? nrm * expf(-0.5f * tt * tt) : 0.f;
        float2 yv = Y2[i];
        v[m] = make_float2(yv.x * h, yv.y * h);
    }
    pass1<true, true>(A, v, t);
    pass2<true>(A, t);
    pass3<true>(A, t);
    pass4<true>(A, A, t);

    // ---- pointwise: P = (|W1|^2 + i|W2|^2)/s, C = W1*conj(W2)/s (C -> X) ----
    const float scf = (1.0f / sc) * (1.0f / ((float)NN * (float)NN));
    float2 pv[8];
    #pragma unroll
    for (int m = 0; m < 8; m++) {
        int idx = (t + 256 * m) ^ mr;
        float2 w1 = X[idx], w2 = A[idx];
        pv[m] = make_float2((w1.x * w1.x + w1.y * w1.y) * scf,
                            (w2.x * w2.x + w2.y * w2.y) * scf);
        X[idx] = make_float2((w1.x * w2.x + w1.y * w2.y) * scf,
                             (w1.y * w2.x - w1.x * w2.y) * scf);
    }

    // ---- FFT3: forward fft of packed P -> A ----
    pass1<false, false>(A, pv, t);
    pass2<false>(A, t);
    pass3<false>(A, t);
    pass4<false>(A, A, t);

    // ---- FFT4: apply Gaussian smoother, inverse fft, write T1/T2 ----
    float sd = sc * 10.0f;
    float a2 = sd * sd;
    const float invN = 1.0f / (float)NN;
    #pragma unroll
    for (int m = 0; m < 8; m++) {
        int i = t + 256 * m;
        int f = (i < 1024) ? i : (NN - i);
        float k = KFAC * (float)f;
        float g = expf(-0.5f * a2 * k * k) * invN;
        float2 a = A[i ^ mr];
        v[m] = make_float2(a.x * g, a.y * g);
    }
    size_t base = ((size_t)pair * NSC + js) * NN;
    pass1<true, false>(A, v, t);
    pass2<true>(A, t);
    pass3<true>(A, t);
    pass4_gT<true>(A, g_T1 + base, g_T2 + base, t);

    // ---- FFT5: forward fft of C (from X) -> A ----
    #pragma unroll
    for (int m = 0; m < 8; m++) v[m] = X[(t + 256 * m) ^ mr];
    pass1<false, false>(A, v, t);
    pass2<false>(A, t);
    pass3<false>(A, t);
    pass4<false>(A, A, t);

    // ---- FFT6: Gaussian smoother + inverse fft, write T12 ----
    #pragma unroll
    for (int m = 0; m < 8; m++) {
        int i = t + 256 * m;
        int f = (i < 1024) ? i : (NN - i);
        float k = KFAC * (float)f;
        float g = expf(-0.5f * a2 * k * k) * invN;
        float2 a = A[i ^ mr];
        v[m] = make_float2(a.x * g, a.y * g);
    }
    pass1<true, false>(A, v, t);
    pass2<true>(A, t);
    pass3<true>(A, t);
    pass4_gC<true>(A, g_T12 + base, t);
}

// ---------------------------------------------------------------------------
// K2: scale smoothing (10-tap, half ends) + coherence + sum over scales.
// 1/9 window normalization cancels in the ratio. grid = 64*64
// ---------------------------------------------------------------------------
__global__ void __launch_bounds__(TPB) k2_coh() {
    __shared__ float s1[NSC * 32], s2[NSC * 32], cr[NSC * 32], ci[NSC * 32];
    __shared__ float scoh[32];
    int blk = blockIdx.x;
    int pair = blk >> 6;
    int t0 = (blk & 63) * 32;
    int tid = threadIdx.x;

    size_t base = (size_t)pair * NSC * NN + t0;
    for (int idx = tid; idx < NSC * 32; idx += TPB) {
        int row = idx >> 5, col = idx & 31;
        size_t g = base + (size_t)row * NN + col;
        s1[idx] = g_T1[g];
        s2[idx] = g_T2[g];
        float2 c = g_T12[g];
        cr[idx] = c.x;
        ci[idx] = c.y;
    }
    if (tid < 32) scoh[tid] = 0.f;
    __syncthreads();

    int tl = tid & 31, jg = tid >> 5;
    float acc = 0.f;
    for (int j = jg; j < NSC; j += 8) {
        float a = 0.f, b = 0.f, c = 0.f, d = 0.f;
        #pragma unroll
        for (int k = 0; k < 10; k++) {
            int r = j + 4 - k;
            if (r >= 0 && r < NSC) {
                float w = (k == 0 || k == 9) ? 0.5f : 1.0f;
                int ix = r * 32 + tl;
                a += w * s1[ix];
                b += w * s2[ix];
                c += w * cr[ix];
                d += w * ci[ix];
            }
        }
        acc += (c * c + d * d) / (a * b);
    }
    atomicAdd(&scoh[tl], acc);
    __syncthreads();
    if (tid < 32) g_coh[(size_t)pair * NN + t0 + tid] = scoh[tid];
}

// ---------------------------------------------------------------------------
// K3: sliding-window sum (window 94) -> out [64, 1955]
// ---------------------------------------------------------------------------
__global__ void __launch_bounds__(TPB) k3_window(float* __restrict__ out) {
    __shared__ float c[NN];
    int pair = blockIdx.x;
    int tid = threadIdx.x;
    for (int i = tid; i < NN; i += TPB) c[i] = g_coh[(size_t)pair * NN + i];
    __syncthreads();
    for (int t = tid; t < NOUT; t += TPB) {
        float s = 0.f;
        for (int k = 0; k < WSZ; k++) s += c[t + k];
        out[(size_t)pair * NOUT + t] = s;
    }
}

// ---------------------------------------------------------------------------
// Entry point
// ---------------------------------------------------------------------------
extern "C" void kernel_launch(void* const* d_in, const int* in_sizes, int n_in,
                              void* d_out, int out_size) {
    (void)in_sizes; (void)n_in; (void)out_size;
    const float* x = (const float*)d_in[0];
    float* out = (float*)d_out;

    k0_normfft<<<NB * 2, TPB>>>(x);
    k1_scale<<<NB * NSC, TPB>>>();
    k2_coh<<<NB * 64, TPB>>>();
    k3_window<<<NB, TPB>>>(out);
}

// round 9
// speedup vs baseline: 1.7166x; 1.2113x over previous
#include <cuda_runtime.h>

// ---------------------------------------------------------------------------
// Problem constants
// ---------------------------------------------------------------------------
#define NN     2048
#define NSC    81
#define NB     64
#define TPB    256
#define WSZ    94
#define NOUT   (NN - WSZ + 1)  // 1955

#define S0F        0.1936026618f            // 2*dt*(w0+sqrt(2+w0^2))/(4*pi)
#define WFAC       0.030679615757712823f    // 2*pi / (2048*0.1)
#define KFAC       0.0030679615757712823f   // 2*pi / 2048
#define TWOPI_F    6.283185307179586f
#define INV_PI4    0.7511255444649425f      // pi^(-1/4)
#define RSQ2       0.70710678118654752f

// ---------------------------------------------------------------------------
// Packed complex type: one 64-bit reg pair holding (re, im) as f32x2
// ---------------------------------------------------------------------------
typedef unsigned long long c64;

__device__ __forceinline__ c64 PKc(float x, float y) {
    c64 r; asm("mov.b64 %0, {%1,%2};" : "=l"(r) : "f"(x), "f"(y)); return r;
}
__device__ __forceinline__ void UPKc(c64 v, float& x, float& y) {
    asm("mov.b64 {%0,%1}, %2;" : "=f"(x), "=f"(y) : "l"(v));
}
__device__ __forceinline__ c64 padd(c64 a, c64 b) {
    c64 r; asm("add.rn.f32x2 %0, %1, %2;" : "=l"(r) : "l"(a), "l"(b)); return r;
}
__device__ __forceinline__ c64 pmul(c64 a, c64 b) {
    c64 r; asm("mul.rn.f32x2 %0, %1, %2;" : "=l"(r) : "l"(a), "l"(b)); return r;
}
__device__ __forceinline__ c64 pfma(c64 a, c64 b, c64 c) {
    c64 r; asm("fma.rn.f32x2 %0, %1, %2, %3;" : "=l"(r) : "l"(a), "l"(b), "l"(c)); return r;
}
__device__ __forceinline__ c64 psub(c64 a, c64 b) { return pfma(b, PKc(-1.f, -1.f), a); }
__device__ __forceinline__ c64 pswap(c64 v) { float x, y; UPKc(v, x, y); return PKc(y, x); }
__device__ __forceinline__ c64 conjc(c64 v) { float x, y; UPKc(v, x, y); return PKc(x, -y); }

// scalar complex multiply on packed values (4 fp instrs)
__device__ __forceinline__ c64 cmulc(c64 a, c64 b) {
    float ax, ay, bx, by; UPKc(a, ax, ay); UPKc(b, bx, by);
    return PKc(fmaf(ax, bx, -ay * by), fmaf(ax, by, ay * bx));
}

// ---------------------------------------------------------------------------
// Scratch (device globals; no allocation anywhere)
// ---------------------------------------------------------------------------
static __device__ c64   g_Y  [NB * 2 * NN];
static __device__ float g_T1 [(size_t)NB * NSC * NN];
static __device__ float g_T2 [(size_t)NB * NSC * NN];
static __device__ c64   g_T12[(size_t)NB * NSC * NN];
static __device__ float g_coh[NB * NN];

// ---------------------------------------------------------------------------
// Bank swizzles (verified conflict-free for all patterns below)
// ---------------------------------------------------------------------------
__device__ __forceinline__ int gmask(int h) { return (h & 7) ^ ((h & 4) << 1); }
__device__ __forceinline__ int sw(int i)    { return i ^ gmask(i >> 4); }
__device__ __forceinline__ int twidx(int k) { return k ^ ((k >> 4) & 15); }

// Twiddle table: logical tw[k] = exp(-i*pi*k/1024), stored bank-permuted.
__device__ __forceinline__ void fill_tw(c64* tw, int tid) {
    #pragma unroll
    for (int k = tid; k < 1024; k += TPB) {
        float s, c;
        sincospif(-(float)k * (1.0f / 1024.0f), &s, &c);
        tw[twidx(k)] = PKc(c, s);
    }
}
template <bool INV>
__device__ __forceinline__ c64 twget(const c64* tw, int k) {
    c64 w = tw[twidx(k)];
    return INV ? conjc(w) : w;
}

// ---------------------------------------------------------------------------
// Packed radix-8 butterflies
// CI1: cadd(b, (+-i)*d) = pfma(swap(d), CI1, b) ; CI2 = opposite sign pair
// ---------------------------------------------------------------------------
template <bool INV>
__device__ __forceinline__ void bf8_tail(c64 E0, c64 E1, c64 E2, c64 E3,
                                         c64 O0, c64 O1, c64 O2, c64 O3,
                                         c64 v[8]) {
    const c64 CI1 = INV ? PKc(-1.f, 1.f) : PKc(1.f, -1.f);
    const c64 CI2 = INV ? PKc(1.f, -1.f) : PKc(-1.f, 1.f);
    const c64 PIM = PKc(-1.f, 1.f);
    // q(O) = (O.x - O.y, O.x + O.y)
    c64 q1 = pfma(pswap(O1), PIM, O1);
    c64 q3 = pfma(pswap(O3), PIM, O3);
    c64 W1 = INV ? pmul(q1, PKc(RSQ2, RSQ2))
                 : pmul(pswap(q1), PKc(RSQ2, -RSQ2));
    c64 W3 = INV ? pmul(pswap(q3), PKc(-RSQ2, RSQ2))
                 : pmul(q3, PKc(-RSQ2, -RSQ2));
    c64 O2s = pswap(O2);
    v[0] = padd(E0, O0);        v[4] = psub(E0, O0);
    v[1] = padd(E1, W1);        v[5] = psub(E1, W1);
    v[2] = pfma(O2s, CI1, E2);  v[6] = pfma(O2s, CI2, E2);
    v[3] = padd(E3, W3);        v[7] = psub(E3, W3);
}

template <bool INV>
__device__ __forceinline__ void bf8(c64 v[8]) {
    const c64 CI1 = INV ? PKc(-1.f, 1.f) : PKc(1.f, -1.f);
    const c64 CI2 = INV ? PKc(1.f, -1.f) : PKc(-1.f, 1.f);
    c64 e0 = padd(v[0], v[4]), e1 = psub(v[0], v[4]);
    c64 e2 = padd(v[2], v[6]), e3 = psub(v[2], v[6]);
    c64 e3s = pswap(e3);
    c64 E0 = padd(e0, e2), E2 = psub(e0, e2);
    c64 E1 = pfma(e3s, CI1, e1), E3 = pfma(e3s, CI2, e1);
    c64 o0 = padd(v[1], v[5]), o1 = psub(v[1], v[5]);
    c64 o2 = padd(v[3], v[7]), o3 = psub(v[3], v[7]);
    c64 o3s = pswap(o3);
    c64 O0 = padd(o0, o2), O2 = psub(o0, o2);
    c64 O1 = pfma(o3s, CI1, o1), O3 = pfma(o3s, CI2, o1);
    bf8_tail<INV>(E0, E1, E2, E3, O0, O1, O2, O3, v);
}

// Half-input butterfly: v[0..3] valid, v[4..7] == 0 (Morlet filter support)
template <bool INV>
__device__ __forceinline__ void bf8h(c64 v[8]) {
    const c64 CI1 = INV ? PKc(-1.f, 1.f) : PKc(1.f, -1.f);
    const c64 CI2 = INV ? PKc(1.f, -1.f) : PKc(-1.f, 1.f);
    c64 a0 = v[0], a1 = v[2], b0 = v[1], b1 = v[3];
    c64 a1s = pswap(a1);
    c64 E0 = padd(a0, a1), E2 = psub(a0, a1);
    c64 E1 = pfma(a1s, CI1, a0), E3 = pfma(a1s, CI2, a0);
    c64 b1s = pswap(b1);
    c64 O0 = padd(b0, b1), O2 = psub(b0, b1);
    c64 O1 = pfma(b1s, CI1, b0), O3 = pfma(b1s, CI2, b0);
    bf8_tail<INV>(E0, E1, E2, E3, O0, O1, O2, O3, v);
}

// ---------------------------------------------------------------------------
// Stockham passes, N = 2048 = 8*8*8*4, 256 threads, in-place swizzled buffer
// ---------------------------------------------------------------------------
template <bool INV, bool HALF>
__device__ __forceinline__ void pass1(c64* A, c64 v[8], int t) {
    __syncthreads();
    if (HALF) bf8h<INV>(v); else bf8<INV>(v);
    int mw = gmask(t >> 1);
    int b8 = 8 * t;
    #pragma unroll
    for (int r = 0; r < 8; r++) A[(b8 + r) ^ mw] = v[r];
    __syncthreads();
}

template <bool INV>
__device__ __forceinline__ void pass2(c64* A, const c64* tw, int t) {
    c64 v[8];
    int mr = gmask(t >> 4);
    #pragma unroll
    for (int m = 0; m < 8; m++) v[m] = A[(t + 256 * m) ^ mr];
    int p = t & 7;
    c64 w1 = twget<INV>(tw, 32 * p);
    c64 w2 = cmulc(w1, w1), w3 = cmulc(w2, w1), w4 = cmulc(w2, w2);
    c64 w5 = cmulc(w3, w2), w6 = cmulc(w3, w3), w7 = cmulc(w4, w3);
    v[1] = cmulc(v[1], w1); v[2] = cmulc(v[2], w2); v[3] = cmulc(v[3], w3);
    v[4] = cmulc(v[4], w4); v[5] = cmulc(v[5], w5); v[6] = cmulc(v[6], w6);
    v[7] = cmulc(v[7], w7);
    __syncthreads();
    bf8<INV>(v);
    int o = (t >> 3) * 64 + p;
    #pragma unroll
    for (int r = 0; r < 8; r++) { int i = o + 8 * r; A[sw(i)] = v[r]; }
    __syncthreads();
}

template <bool INV>
__device__ __forceinline__ void pass3(c64* A, const c64* tw, int t) {
    c64 v[8];
    int mr = gmask(t >> 4);
    #pragma unroll
    for (int m = 0; m < 8; m++) v[m] = A[(t + 256 * m) ^ mr];
    int p = t & 63;
    c64 w1 = twget<INV>(tw, 4 * p);
    c64 w2 = cmulc(w1, w1), w3 = cmulc(w2, w1), w4 = cmulc(w2, w2);
    c64 w5 = cmulc(w3, w2), w6 = cmulc(w3, w3), w7 = cmulc(w4, w3);
    v[1] = cmulc(v[1], w1); v[2] = cmulc(v[2], w2); v[3] = cmulc(v[3], w3);
    v[4] = cmulc(v[4], w4); v[5] = cmulc(v[5], w5); v[6] = cmulc(v[6], w6);
    v[7] = cmulc(v[7], w7);
    __syncthreads();
    bf8<INV>(v);
    int o = (t >> 6) * 512 + p;
    #pragma unroll
    for (int r = 0; r < 8; r++) { int i = o + 64 * r; A[sw(i)] = v[r]; }
    __syncthreads();
}

// Final radix-4 pass (NSv=512): two butterflies per thread
template <bool INV>
__device__ __forceinline__ void pass4_core(const c64* A, const c64* tw, int t, c64 u[2][4]) {
    const c64 CI1 = INV ? PKc(-1.f, 1.f) : PKc(1.f, -1.f);
    const c64 CI2 = INV ? PKc(1.f, -1.f) : PKc(-1.f, 1.f);
    #pragma unroll
    for (int b = 0; b < 2; b++) {
        int j = t + 256 * b;
        int mr = gmask(j >> 4);
        c64 v0 = A[j ^ mr];
        c64 v1 = A[(j + 512) ^ mr];
        c64 v2 = A[(j + 1024) ^ mr];
        c64 v3 = A[(j + 1536) ^ mr];
        c64 w1 = twget<INV>(tw, j);
        c64 w2 = cmulc(w1, w1), w3 = cmulc(w2, w1);
        v1 = cmulc(v1, w1); v2 = cmulc(v2, w2); v3 = cmulc(v3, w3);
        c64 aa = padd(v0, v2), bb = psub(v0, v2);
        c64 cc = padd(v1, v3), dd = psub(v1, v3);
        c64 ds = pswap(dd);
        u[b][0] = padd(aa, cc);        u[b][2] = psub(aa, cc);
        u[b][1] = pfma(ds, CI1, bb);   u[b][3] = pfma(ds, CI2, bb);
    }
}

template <bool INV>
__device__ __forceinline__ void pass4(const c64* A, c64* D, const c64* tw, int t) {
    c64 u[2][4];
    pass4_core<INV>(A, tw, t, u);
    __syncthreads();
    #pragma unroll
    for (int b = 0; b < 2; b++) {
        int j = t + 256 * b;
        int mw = gmask(j >> 4);
        #pragma unroll
        for (int r = 0; r < 4; r++) D[(j + 512 * r) ^ mw] = u[b][r];
    }
    __syncthreads();
}

template <bool INV>
__device__ __forceinline__ void pass4_gT(const c64* A, const c64* tw,
                                         float* T1, float* T2, int t) {
    c64 u[2][4];
    pass4_core<INV>(A, tw, t, u);
    #pragma unroll
    for (int b = 0; b < 2; b++) {
        int j = t + 256 * b;
        #pragma unroll
        for (int r = 0; r < 4; r++) {
            float x, y; UPKc(u[b][r], x, y);
            T1[j + 512 * r] = x; T2[j + 512 * r] = y;
        }
    }
}

template <bool INV>
__device__ __forceinline__ void pass4_gC(const c64* A, const c64* tw, c64* T12, int t) {
    c64 u[2][4];
    pass4_core<INV>(A, tw, t, u);
    #pragma unroll
    for (int b = 0; b < 2; b++) {
        int j = t + 256 * b;
        #pragma unroll
        for (int r = 0; r < 4; r++) T12[j + 512 * r] = u[b][r];
    }
}

// ---------------------------------------------------------------------------
// Block reduction (256 threads)
// ---------------------------------------------------------------------------
__device__ __forceinline__ float block_reduce(float v, float* red) {
    int tid = threadIdx.x;
    #pragma unroll
    for (int o = 16; o > 0; o >>= 1) v += __shfl_xor_sync(0xffffffffu, v, o);
    if ((tid & 31) == 0) red[tid >> 5] = v;
    __syncthreads();
    if (tid < 32) {
        float r = (tid < TPB / 32) ? red[tid] : 0.f;
        #pragma unroll
        for (int o = 4; o > 0; o >>= 1) r += __shfl_xor_sync(0xffffffffu, r, o);
        if (tid == 0) red[32] = r;
    }
    __syncthreads();
    float r = red[32];
    __syncthreads();
    return r;
}

// ---------------------------------------------------------------------------
// K0: normalize each signal + forward FFT -> g_Y.  grid = 128
// ---------------------------------------------------------------------------
__global__ void __launch_bounds__(TPB) k0_normfft(const float* __restrict__ x) {
    __shared__ c64 A[NN];
    __shared__ c64 tw[1024];
    __shared__ float red[33];
    int b = blockIdx.x, t = threadIdx.x;
    const float* y = x + (size_t)b * NN;

    fill_tw(tw, t);

    float s = 0.f;
    #pragma unroll
    for (int i = t; i < NN; i += TPB) s += y[i];
    float mean = block_reduce(s, red) * (1.0f / NN);

    float vv = 0.f;
    #pragma unroll
    for (int i = t; i < NN; i += TPB) { float d = y[i] - mean; vv += d * d; }
    float istd = rsqrtf(block_reduce(vv, red) * (1.0f / NN));

    c64 v[8];
    #pragma unroll
    for (int m = 0; m < 8; m++) {
        int i = t + 256 * m;
        v[m] = PKc((y[i] - mean) * istd, 0.f);
    }
    pass1<false, false>(A, v, t);
    pass2<false>(A, tw, t);
    pass3<false>(A, tw, t);
    pass4<false>(A, A, tw, t);

    int mr = gmask(t >> 4);
    c64* out = g_Y + (size_t)b * NN;
    #pragma unroll
    for (int m = 0; m < 8; m++) { int i = t + 256 * m; out[i] = A[i ^ mr]; }
}

// ---------------------------------------------------------------------------
// K1: per (pair, scale) full chain with fused pointwise ops. grid = 5184
// ---------------------------------------------------------------------------
__global__ void __launch_bounds__(TPB, 4) k1_scale() {
    __shared__ c64 A[NN];
    __shared__ c64 X[NN];
    __shared__ c64 tw[1024];
    int blk = blockIdx.x;
    int pair = blk / NSC;
    int js = blk - pair * NSC;
    int t = threadIdx.x;

    fill_tw(tw, t);

    float sc  = S0F * exp2f(0.125f * (float)js);
    float nrm = sqrtf(TWOPI_F * sc * 10.0f) * INV_PI4;
    const c64* Y1 = g_Y + (size_t)pair * 2 * NN;
    const c64* Y2 = Y1 + NN;
    int mr = gmask(t >> 4);

    c64 v[8];

    // ---- FFT1: W1 = unscaled ifft(Y1*H)  (H zero for bins >= 1024) -> X ----
    #pragma unroll
    for (int m = 0; m < 4; m++) {
        int i = t + 256 * m;
        float tt = sc * (WFAC * (float)i) - 6.0f;
        float h = (i >= 1) ? nrm * expf(-0.5f * tt * tt) : 0.f;
        v[m] = pmul(Y1[i], PKc(h, h));
    }
    pass1<true, true>(A, v, t);
    pass2<true>(A, tw, t);
    pass3<true>(A, tw, t);
    pass4<true>(A, X, tw, t);

    // ---- FFT2: W2 -> A ----
    #pragma unroll
    for (int m = 0; m < 4; m++) {
        int i = t + 256 * m;
        float tt = sc * (WFAC * (float)i) - 6.0f;
        float h = (i >= 1) ? nrm * expf(-0.5f * tt * tt) : 0.f;
        v[m] = pmul(Y2[i], PKc(h, h));
    }
    pass1<true, true>(A, v, t);
    pass2<true>(A, tw, t);
    pass3<true>(A, tw, t);
    pass4<true>(A, A, tw, t);

    // ---- pointwise: P = (|W1|^2 + i|W2|^2)/s, C = W1*conj(W2)/s (C -> X) ----
    const float scf = (1.0f / sc) * (1.0f / ((float)NN * (float)NN));
    c64 pv[8];
    #pragma unroll
    for (int m = 0; m < 8; m++) {
        int idx = (t + 256 * m) ^ mr;
        float w1x, w1y, w2x, w2y;
        UPKc(X[idx], w1x, w1y);
        UPKc(A[idx], w2x, w2y);
        pv[m] = PKc((w1x * w1x + w1y * w1y) * scf,
                    (w2x * w2x + w2y * w2y) * scf);
        X[idx] = PKc((w1x * w2x + w1y * w2y) * scf,
                     (w1y * w2x - w1x * w2y) * scf);
    }

    // ---- FFT3: forward fft of packed P -> A ----
    pass1<false, false>(A, pv, t);
    pass2<false>(A, tw, t);
    pass3<false>(A, tw, t);
    pass4<false>(A, A, tw, t);

    // ---- FFT4: Gaussian smoother + inverse fft, write T1/T2 ----
    float sd = sc * 10.0f;
    float a2 = sd * sd;
    const float invN = 1.0f / (float)NN;
    #pragma unroll
    for (int m = 0; m < 8; m++) {
        int i = t + 256 * m;
        int f = (i < 1024) ? i : (NN - i);
        float k = KFAC * (float)f;
        float g = expf(-0.5f * a2 * k * k) * invN;
        v[m] = pmul(A[i ^ mr], PKc(g, g));
    }
    size_t base = ((size_t)pair * NSC + js) * NN;
    pass1<true, false>(A, v, t);
    pass2<true>(A, tw, t);
    pass3<true>(A, tw, t);
    pass4_gT<true>(A, tw, g_T1 + base, g_T2 + base, t);

    // ---- FFT5: forward fft of C (from X) -> A ----
    #pragma unroll
    for (int m = 0; m < 8; m++) v[m] = X[(t + 256 * m) ^ mr];
    pass1<false, false>(A, v, t);
    pass2<false>(A, tw, t);
    pass3<false>(A, tw, t);
    pass4<false>(A, A, tw, t);

    // ---- FFT6: Gaussian smoother + inverse fft, write T12 ----
    #pragma unroll
    for (int m = 0; m < 8; m++) {
        int i = t + 256 * m;
        int f = (i < 1024) ? i : (NN - i);
        float k = KFAC * (float)f;
        float g = expf(-0.5f * a2 * k * k) * invN;
        v[m] = pmul(A[i ^ mr], PKc(g, g));
    }
    pass1<true, false>(A, v, t);
    pass2<true>(A, tw, t);
    pass3<true>(A, tw, t);
    pass4_gC<true>(A, tw, g_T12 + base, t);
}

// ---------------------------------------------------------------------------
// K2: scale smoothing (10-tap, half ends) + coherence + sum over scales.
// 1/9 window normalization cancels in the ratio. grid = 64*64
// ---------------------------------------------------------------------------
__global__ void __launch_bounds__(TPB) k2_coh() {
    __shared__ float s1[NSC * 32], s2[NSC * 32], cr[NSC * 32], ci[NSC * 32];
    __shared__ float scoh[32];
    int blk = blockIdx.x;
    int pair = blk >> 6;
    int t0 = (blk & 63) * 32;
    int tid = threadIdx.x;

    size_t base = (size_t)pair * NSC * NN + t0;
    for (int idx = tid; idx < NSC * 32; idx += TPB) {
        int row = idx >> 5, col = idx & 31;
        size_t g = base + (size_t)row * NN + col;
        s1[idx] = g_T1[g];
        s2[idx] = g_T2[g];
        float cx, cy; UPKc(g_T12[g], cx, cy);
        cr[idx] = cx;
        ci[idx] = cy;
    }
    if (tid < 32) scoh[tid] = 0.f;
    __syncthreads();

    int tl = tid & 31, jg = tid >> 5;
    float acc = 0.f;
    for (int j = jg; j < NSC; j += 8) {
        float a = 0.f, b = 0.f, c = 0.f, d = 0.f;
        #pragma unroll
        for (int k = 0; k < 10; k++) {
            int r = j + 4 - k;
            if (r >= 0 && r < NSC) {
                float w = (k == 0 || k == 9) ? 0.5f : 1.0f;
                int ix = r * 32 + tl;
                a += w * s1[ix];
                b += w * s2[ix];
                c += w * cr[ix];
                d += w * ci[ix];
            }
        }
        acc += (c * c + d * d) / (a * b);
    }
    atomicAdd(&scoh[tl], acc);
    __syncthreads();
    if (tid < 32) g_coh[(size_t)pair * NN + t0 + tid] = scoh[tid];
}

// ---------------------------------------------------------------------------
// K3: sliding-window sum (window 94) -> out [64, 1955]. grid = 64*8 tiles
// ---------------------------------------------------------------------------
__global__ void __launch_bounds__(TPB) k3_window(float* __restrict__ out) {
    __shared__ float c[TPB + WSZ];
    int pair = blockIdx.x >> 3;
    int t0 = (blockIdx.x & 7) * TPB;
    int tid = threadIdx.x;
    for (int i = tid; i < TPB + WSZ; i += TPB) {
        int g = t0 + i;
        c[i] = (g < NN) ? g_coh[(size_t)pair * NN + g] : 0.f;
    }
    __syncthreads();
    int t = t0 + tid;
    if (t < NOUT) {
        float s = 0.f;
        #pragma unroll
        for (int k = 0; k < WSZ; k++) s += c[tid + k];
        out[(size_t)pair * NOUT + t] = s;
    }
}

// ---------------------------------------------------------------------------
// Entry point
// ---------------------------------------------------------------------------
extern "C" void kernel_launch(void* const* d_in, const int* in_sizes, int n_in,
                              void* d_out, int out_size) {
    (void)in_sizes; (void)n_in; (void)out_size;
    const float* x = (const float*)d_in[0];
    float* out = (float*)d_out;

    k0_normfft<<<NB * 2, TPB>>>(x);
    k1_scale<<<NB * NSC, TPB>>>();
    k2_coh<<<NB * 64, TPB>>>();
    k3_window<<<NB * 8, TPB>>>(out);
}

// round 10
// speedup vs baseline: 1.8387x; 1.0711x over previous
#include <cuda_runtime.h>

// ---------------------------------------------------------------------------
// Problem constants
// ---------------------------------------------------------------------------
#define NN     2048
#define NSC    81
#define NB     64
#define TPB    256
#define WSZ    94
#define NOUT   (NN - WSZ + 1)  // 1955

#define S0F        0.1936026618f            // 2*dt*(w0+sqrt(2+w0^2))/(4*pi)
#define WFAC       0.030679615757712823f    // 2*pi / (2048*0.1)
#define KFAC       0.0030679615757712823f   // 2*pi / 2048
#define TWOPI_F    6.283185307179586f
#define INV_PI4    0.7511255444649425f      // pi^(-1/4)
#define RSQ2       0.70710678118654752f

// ---------------------------------------------------------------------------
// Packed complex type: one 64-bit reg pair holding (re, im) as f32x2
// ---------------------------------------------------------------------------
typedef unsigned long long c64;

__device__ __forceinline__ c64 PKc(float x, float y) {
    c64 r; asm("mov.b64 %0, {%1,%2};" : "=l"(r) : "f"(x), "f"(y)); return r;
}
__device__ __forceinline__ void UPKc(c64 v, float& x, float& y) {
    asm("mov.b64 {%0,%1}, %2;" : "=f"(x), "=f"(y) : "l"(v));
}
__device__ __forceinline__ c64 padd(c64 a, c64 b) {
    c64 r; asm("add.rn.f32x2 %0, %1, %2;" : "=l"(r) : "l"(a), "l"(b)); return r;
}
__device__ __forceinline__ c64 pmul(c64 a, c64 b) {
    c64 r; asm("mul.rn.f32x2 %0, %1, %2;" : "=l"(r) : "l"(a), "l"(b)); return r;
}
__device__ __forceinline__ c64 pfma(c64 a, c64 b, c64 c) {
    c64 r; asm("fma.rn.f32x2 %0, %1, %2, %3;" : "=l"(r) : "l"(a), "l"(b), "l"(c)); return r;
}
__device__ __forceinline__ c64 psub(c64 a, c64 b) { return pfma(b, PKc(-1.f, -1.f), a); }
__device__ __forceinline__ c64 pswap(c64 v) { float x, y; UPKc(v, x, y); return PKc(y, x); }
__device__ __forceinline__ c64 conjc(c64 v) { float x, y; UPKc(v, x, y); return PKc(x, -y); }

// scalar complex multiply on packed values (4 fp instrs)
__device__ __forceinline__ c64 cmulc(c64 a, c64 b) {
    float ax, ay, bx, by; UPKc(a, ax, ay); UPKc(b, bx, by);
    return PKc(fmaf(ax, bx, -ay * by), fmaf(ax, by, ay * bx));
}

// ---------------------------------------------------------------------------
// Scratch (device globals; no allocation anywhere)
// ---------------------------------------------------------------------------
static __device__ c64   g_Y  [NB * 2 * NN];
static __device__ float g_T1 [(size_t)NB * NSC * NN];
static __device__ float g_T2 [(size_t)NB * NSC * NN];
static __device__ c64   g_T12[(size_t)NB * NSC * NN];
static __device__ float g_coh[NB * NN];

// ---------------------------------------------------------------------------
// Bank swizzles (verified conflict-free for all patterns below)
// ---------------------------------------------------------------------------
__device__ __forceinline__ int gmask(int h) { return (h & 7) ^ ((h & 4) << 1); }
__device__ __forceinline__ int sw(int i)    { return i ^ gmask(i >> 4); }
__device__ __forceinline__ int twidx(int k) { return k ^ ((k >> 4) & 15); }

// Twiddle table: logical tw[k] = exp(-i*pi*k/1024), stored bank-permuted.
__device__ __forceinline__ void fill_tw(c64* tw, int tid) {
    #pragma unroll
    for (int k = tid; k < 1024; k += TPB) {
        float s, c;
        sincospif(-(float)k * (1.0f / 1024.0f), &s, &c);
        tw[twidx(k)] = PKc(c, s);
    }
}
template <bool INV>
__device__ __forceinline__ c64 twget(const c64* tw, int k) {
    c64 w = tw[twidx(k)];
    return INV ? conjc(w) : w;
}

// ---------------------------------------------------------------------------
// Packed radix-8 butterflies
// ---------------------------------------------------------------------------
template <bool INV>
__device__ __forceinline__ void bf8_tail(c64 E0, c64 E1, c64 E2, c64 E3,
                                         c64 O0, c64 O1, c64 O2, c64 O3,
                                         c64 v[8]) {
    const c64 CI1 = INV ? PKc(-1.f, 1.f) : PKc(1.f, -1.f);
    const c64 CI2 = INV ? PKc(1.f, -1.f) : PKc(-1.f, 1.f);
    const c64 PIM = PKc(-1.f, 1.f);
    c64 q1 = pfma(pswap(O1), PIM, O1);
    c64 q3 = pfma(pswap(O3), PIM, O3);
    c64 W1 = INV ? pmul(q1, PKc(RSQ2, RSQ2))
                 : pmul(pswap(q1), PKc(RSQ2, -RSQ2));
    c64 W3 = INV ? pmul(pswap(q3), PKc(-RSQ2, RSQ2))
                 : pmul(q3, PKc(-RSQ2, -RSQ2));
    c64 O2s = pswap(O2);
    v[0] = padd(E0, O0);        v[4] = psub(E0, O0);
    v[1] = padd(E1, W1);        v[5] = psub(E1, W1);
    v[2] = pfma(O2s, CI1, E2);  v[6] = pfma(O2s, CI2, E2);
    v[3] = padd(E3, W3);        v[7] = psub(E3, W3);
}

template <bool INV>
__device__ __forceinline__ void bf8(c64 v[8]) {
    const c64 CI1 = INV ? PKc(-1.f, 1.f) : PKc(1.f, -1.f);
    const c64 CI2 = INV ? PKc(1.f, -1.f) : PKc(-1.f, 1.f);
    c64 e0 = padd(v[0], v[4]), e1 = psub(v[0], v[4]);
    c64 e2 = padd(v[2], v[6]), e3 = psub(v[2], v[6]);
    c64 e3s = pswap(e3);
    c64 E0 = padd(e0, e2), E2 = psub(e0, e2);
    c64 E1 = pfma(e3s, CI1, e1), E3 = pfma(e3s, CI2, e1);
    c64 o0 = padd(v[1], v[5]), o1 = psub(v[1], v[5]);
    c64 o2 = padd(v[3], v[7]), o3 = psub(v[3], v[7]);
    c64 o3s = pswap(o3);
    c64 O0 = padd(o0, o2), O2 = psub(o0, o2);
    c64 O1 = pfma(o3s, CI1, o1), O3 = pfma(o3s, CI2, o1);
    bf8_tail<INV>(E0, E1, E2, E3, O0, O1, O2, O3, v);
}

// Half-input butterfly: v[0..3] valid, v[4..7] == 0 (Morlet filter support)
template <bool INV>
__device__ __forceinline__ void bf8h(c64 v[8]) {
    const c64 CI1 = INV ? PKc(-1.f, 1.f) : PKc(1.f, -1.f);
    const c64 CI2 = INV ? PKc(1.f, -1.f) : PKc(-1.f, 1.f);
    c64 a0 = v[0], a1 = v[2], b0 = v[1], b1 = v[3];
    c64 a1s = pswap(a1);
    c64 E0 = padd(a0, a1), E2 = psub(a0, a1);
    c64 E1 = pfma(a1s, CI1, a0), E3 = pfma(a1s, CI2, a0);
    c64 b1s = pswap(b1);
    c64 O0 = padd(b0, b1), O2 = psub(b0, b1);
    c64 O1 = pfma(b1s, CI1, b0), O3 = pfma(b1s, CI2, b0);
    bf8_tail<INV>(E0, E1, E2, E3, O0, O1, O2, O3, v);
}

// ---------------------------------------------------------------------------
// Stockham passes, N = 2048 = 8*8*8*4, 256 threads, in-place swizzled buffer.
// Thread t's register set v[m] always maps to logical positions t + 256*m at
// FFT boundaries — pass4_regs feeds pass1 (and any elementwise op) directly.
// ---------------------------------------------------------------------------
template <bool INV, bool HALF>
__device__ __forceinline__ void pass1(c64* A, c64 v[8], int t) {
    __syncthreads();           // prior readers of A are done
    if (HALF) bf8h<INV>(v); else bf8<INV>(v);
    int mw = gmask(t >> 1);
    int b8 = 8 * t;
    #pragma unroll
    for (int r = 0; r < 8; r++) A[(b8 + r) ^ mw] = v[r];
    __syncthreads();
}

template <bool INV>
__device__ __forceinline__ void pass2(c64* A, const c64* tw, int t) {
    c64 v[8];
    int mr = gmask(t >> 4);
    #pragma unroll
    for (int m = 0; m < 8; m++) v[m] = A[(t + 256 * m) ^ mr];
    int p = t & 7;
    c64 w1 = twget<INV>(tw, 32 * p);
    c64 w2 = cmulc(w1, w1), w3 = cmulc(w2, w1), w4 = cmulc(w2, w2);
    c64 w5 = cmulc(w3, w2), w6 = cmulc(w3, w3), w7 = cmulc(w4, w3);
    v[1] = cmulc(v[1], w1); v[2] = cmulc(v[2], w2); v[3] = cmulc(v[3], w3);
    v[4] = cmulc(v[4], w4); v[5] = cmulc(v[5], w5); v[6] = cmulc(v[6], w6);
    v[7] = cmulc(v[7], w7);
    __syncthreads();
    bf8<INV>(v);
    int o = (t >> 3) * 64 + p;
    #pragma unroll
    for (int r = 0; r < 8; r++) { int i = o + 8 * r; A[sw(i)] = v[r]; }
    __syncthreads();
}

template <bool INV>
__device__ __forceinline__ void pass3(c64* A, const c64* tw, int t) {
    c64 v[8];
    int mr = gmask(t >> 4);
    #pragma unroll
    for (int m = 0; m < 8; m++) v[m] = A[(t + 256 * m) ^ mr];
    int p = t & 63;
    c64 w1 = twget<INV>(tw, 4 * p);
    c64 w2 = cmulc(w1, w1), w3 = cmulc(w2, w1), w4 = cmulc(w2, w2);
    c64 w5 = cmulc(w3, w2), w6 = cmulc(w3, w3), w7 = cmulc(w4, w3);
    v[1] = cmulc(v[1], w1); v[2] = cmulc(v[2], w2); v[3] = cmulc(v[3], w3);
    v[4] = cmulc(v[4], w4); v[5] = cmulc(v[5], w5); v[6] = cmulc(v[6], w6);
    v[7] = cmulc(v[7], w7);
    __syncthreads();
    bf8<INV>(v);
    int o = (t >> 6) * 512 + p;
    #pragma unroll
    for (int r = 0; r < 8; r++) { int i = o + 64 * r; A[sw(i)] = v[r]; }
    __syncthreads();
}

// Final radix-4 pass (NSv=512): RESULT IN REGISTERS, v[m] <-> position t+256m.
// No trailing sync — the next pass1's leading sync protects A.
template <bool INV>
__device__ __forceinline__ void pass4_regs(const c64* A, const c64* tw, int t, c64 v[8]) {
    const c64 CI1 = INV ? PKc(-1.f, 1.f) : PKc(1.f, -1.f);
    const c64 CI2 = INV ? PKc(1.f, -1.f) : PKc(-1.f, 1.f);
    #pragma unroll
    for (int b = 0; b < 2; b++) {
        int j = t + 256 * b;
        int mr = gmask(j >> 4);
        c64 v0 = A[j ^ mr];
        c64 v1 = A[(j + 512) ^ mr];
        c64 v2 = A[(j + 1024) ^ mr];
        c64 v3 = A[(j + 1536) ^ mr];
        c64 w1 = twget<INV>(tw, j);
        c64 w2 = cmulc(w1, w1), w3 = cmulc(w2, w1);
        v1 = cmulc(v1, w1); v2 = cmulc(v2, w2); v3 = cmulc(v3, w3);
        c64 aa = padd(v0, v2), bb = psub(v0, v2);
        c64 cc = padd(v1, v3), dd = psub(v1, v3);
        c64 ds = pswap(dd);
        // output position j + 512*r  ->  m = b + 2*r
        v[b + 0] = padd(aa, cc);       v[b + 4] = psub(aa, cc);
        v[b + 2] = pfma(ds, CI1, bb);  v[b + 6] = pfma(ds, CI2, bb);
    }
}

// Final pass for k0: store to smem (swizzled) so block can copy to global.
template <bool INV>
__device__ __forceinline__ void pass4(c64* A, const c64* tw, int t) {
    c64 v[8];
    pass4_regs<INV>(A, tw, t, v);
    __syncthreads();
    int mr = gmask(t >> 4);
    #pragma unroll
    for (int m = 0; m < 8; m++) A[(t + 256 * m) ^ mr] = v[m];
    __syncthreads();
}

// Final passes writing results straight to global (coalesced), no syncs.
template <bool INV>
__device__ __forceinline__ void pass4_gT(const c64* A, const c64* tw,
                                         float* T1, float* T2, int t) {
    c64 v[8];
    pass4_regs<INV>(A, tw, t, v);
    #pragma unroll
    for (int m = 0; m < 8; m++) {
        float x, y; UPKc(v[m], x, y);
        T1[t + 256 * m] = x; T2[t + 256 * m] = y;
    }
}

template <bool INV>
__device__ __forceinline__ void pass4_gC(const c64* A, const c64* tw, c64* T12, int t) {
    c64 v[8];
    pass4_regs<INV>(A, tw, t, v);
    #pragma unroll
    for (int m = 0; m < 8; m++) T12[t + 256 * m] = v[m];
}

// ---------------------------------------------------------------------------
// Block reduction (256 threads)
// ---------------------------------------------------------------------------
__device__ __forceinline__ float block_reduce(float v, float* red) {
    int tid = threadIdx.x;
    #pragma unroll
    for (int o = 16; o > 0; o >>= 1) v += __shfl_xor_sync(0xffffffffu, v, o);
    if ((tid & 31) == 0) red[tid >> 5] = v;
    __syncthreads();
    if (tid < 32) {
        float r = (tid < TPB / 32) ? red[tid] : 0.f;
        #pragma unroll
        for (int o = 4; o > 0; o >>= 1) r += __shfl_xor_sync(0xffffffffu, r, o);
        if (tid == 0) red[32] = r;
    }
    __syncthreads();
    float r = red[32];
    __syncthreads();
    return r;
}

// ---------------------------------------------------------------------------
// K0: normalize each signal + forward FFT -> g_Y.  grid = 128
// ---------------------------------------------------------------------------
__global__ void __launch_bounds__(TPB) k0_normfft(const float* __restrict__ x) {
    __shared__ c64 A[NN];
    __shared__ c64 tw[1024];
    __shared__ float red[33];
    int b = blockIdx.x, t = threadIdx.x;
    const float* y = x + (size_t)b * NN;

    fill_tw(tw, t);

    float s = 0.f;
    #pragma unroll
    for (int i = t; i < NN; i += TPB) s += y[i];
    float mean = block_reduce(s, red) * (1.0f / NN);

    float vv = 0.f;
    #pragma unroll
    for (int i = t; i < NN; i += TPB) { float d = y[i] - mean; vv += d * d; }
    float istd = rsqrtf(block_reduce(vv, red) * (1.0f / NN));

    c64 v[8];
    #pragma unroll
    for (int m = 0; m < 8; m++) {
        int i = t + 256 * m;
        v[m] = PKc((y[i] - mean) * istd, 0.f);
    }
    pass1<false, false>(A, v, t);
    pass2<false>(A, tw, t);
    pass3<false>(A, tw, t);
    pass4<false>(A, tw, t);

    int mr = gmask(t >> 4);
    c64* out = g_Y + (size_t)b * NN;
    #pragma unroll
    for (int m = 0; m < 8; m++) { int i = t + 256 * m; out[i] = A[i ^ mr]; }
}

// ---------------------------------------------------------------------------
// K1: per (pair, scale) full chain; all FFT junctions chained in registers.
// grid = 5184
// ---------------------------------------------------------------------------
__global__ void __launch_bounds__(TPB, 4) k1_scale() {
    __shared__ c64 A[NN];
    __shared__ c64 X[NN];      // stash: W1, then C (linear layout, conflict-free)
    __shared__ c64 tw[1024];
    int blk = blockIdx.x;
    int pair = blk / NSC;
    int js = blk - pair * NSC;
    int t = threadIdx.x;

    fill_tw(tw, t);

    float sc  = S0F * exp2f(0.125f * (float)js);
    float nrm = sqrtf(TWOPI_F * sc * 10.0f) * INV_PI4;
    const c64* Y1 = g_Y + (size_t)pair * 2 * NN;
    const c64* Y2 = Y1 + NN;

    c64 v[8];

    // Morlet filter values for this thread's 4 low-half bins (reused for both CWTs)
    float hh[4];
    #pragma unroll
    for (int m = 0; m < 4; m++) {
        int i = t + 256 * m;
        float tt = sc * (WFAC * (float)i) - 6.0f;
        hh[m] = (i >= 1) ? nrm * __expf(-0.5f * tt * tt) : 0.f;
    }

    // ---- FFT1: W1 = unscaled ifft(Y1*H) -> stash to X ----
    #pragma unroll
    for (int m = 0; m < 4; m++) v[m] = pmul(Y1[t + 256 * m], PKc(hh[m], hh[m]));
    pass1<true, true>(A, v, t);
    pass2<true>(A, tw, t);
    pass3<true>(A, tw, t);
    pass4_regs<true>(A, tw, t, v);
    #pragma unroll
    for (int m = 0; m < 8; m++) X[t + 256 * m] = v[m];   // same-thread stash

    // ---- FFT2: W2 (in registers at the end) ----
    #pragma unroll
    for (int m = 0; m < 4; m++) v[m] = pmul(Y2[t + 256 * m], PKc(hh[m], hh[m]));
    pass1<true, true>(A, v, t);
    pass2<true>(A, tw, t);
    pass3<true>(A, tw, t);
    pass4_regs<true>(A, tw, t, v);                        // v = W2

    // ---- pointwise: pv = (|W1|^2 + i|W2|^2)/s -> regs;  C = W1*conj(W2)/s -> X
    const float scf = (1.0f / sc) * (1.0f / ((float)NN * (float)NN));
    #pragma unroll
    for (int m = 0; m < 8; m++) {
        float w1x, w1y, w2x, w2y;
        UPKc(X[t + 256 * m], w1x, w1y);                   // same-thread reload
        UPKc(v[m], w2x, w2y);
        X[t + 256 * m] = PKc((w1x * w2x + w1y * w2y) * scf,
                             (w1y * w2x - w1x * w2y) * scf);
        v[m] = PKc((w1x * w1x + w1y * w1y) * scf,
                   (w2x * w2x + w2y * w2y) * scf);
    }

    // ---- FFT3: forward fft of packed P (register input) ----
    pass1<false, false>(A, v, t);
    pass2<false>(A, tw, t);
    pass3<false>(A, tw, t);
    pass4_regs<false>(A, tw, t, v);

    // ---- Gaussian smoother in registers ----
    float sd = sc * 10.0f;
    float a2 = sd * sd;
    const float invN = 1.0f / (float)NN;
    #pragma unroll
    for (int m = 0; m < 8; m++) {
        int i = t + 256 * m;
        int f = (i < 1024) ? i : (NN - i);
        float k = KFAC * (float)f;
        float g = __expf(-0.5f * a2 * k * k) * invN;
        v[m] = pmul(v[m], PKc(g, g));
    }

    // ---- FFT4: inverse fft, write T1/T2 straight to global ----
    size_t base = ((size_t)pair * NSC + js) * NN;
    pass1<true, false>(A, v, t);
    pass2<true>(A, tw, t);
    pass3<true>(A, tw, t);
    pass4_gT<true>(A, tw, g_T1 + base, g_T2 + base, t);

    // ---- FFT5: forward fft of C (same-thread reload from X) ----
    #pragma unroll
    for (int m = 0; m < 8; m++) v[m] = X[t + 256 * m];
    pass1<false, false>(A, v, t);
    pass2<false>(A, tw, t);
    pass3<false>(A, tw, t);
    pass4_regs<false>(A, tw, t, v);

    // ---- Gaussian + FFT6: inverse fft, write T12 ----
    #pragma unroll
    for (int m = 0; m < 8; m++) {
        int i = t + 256 * m;
        int f = (i < 1024) ? i : (NN - i);
        float k = KFAC * (float)f;
        float g = __expf(-0.5f * a2 * k * k) * invN;
        v[m] = pmul(v[m], PKc(g, g));
    }
    pass1<true, false>(A, v, t);
    pass2<true>(A, tw, t);
    pass3<true>(A, tw, t);
    pass4_gC<true>(A, tw, g_T12 + base, t);
}

// ---------------------------------------------------------------------------
// K2: scale smoothing (10-tap, half ends) + coherence + sum over scales.
// 1/9 window normalization cancels in the ratio. grid = 64*64
// ---------------------------------------------------------------------------
__global__ void __launch_bounds__(TPB) k2_coh() {
    __shared__ float s1[NSC * 32], s2[NSC * 32], cr[NSC * 32], ci[NSC * 32];
    __shared__ float scoh[32];
    int blk = blockIdx.x;
    int pair = blk >> 6;
    int t0 = (blk & 63) * 32;
    int tid = threadIdx.x;

    size_t base = (size_t)pair * NSC * NN + t0;
    for (int idx = tid; idx < NSC * 32; idx += TPB) {
        int row = idx >> 5, col = idx & 31;
        size_t g = base + (size_t)row * NN + col;
        s1[idx] = g_T1[g];
        s2[idx] = g_T2[g];
        float cx, cy; UPKc(g_T12[g], cx, cy);
        cr[idx] = cx;
        ci[idx] = cy;
    }
    if (tid < 32) scoh[tid] = 0.f;
    __syncthreads();

    int tl = tid & 31, jg = tid >> 5;
    float acc = 0.f;
    for (int j = jg; j < NSC; j += 8) {
        float a = 0.f, b = 0.f, c = 0.f, d = 0.f;
        #pragma unroll
        for (int k = 0; k < 10; k++) {
            int r = j + 4 - k;
            if (r >= 0 && r < NSC) {
                float w = (k == 0 || k == 9) ? 0.5f : 1.0f;
                int ix = r * 32 + tl;
                a += w * s1[ix];
                b += w * s2[ix];
                c += w * cr[ix];
                d += w * ci[ix];
            }
        }
        acc += (c * c + d * d) / (a * b);
    }
    atomicAdd(&scoh[tl], acc);
    __syncthreads();
    if (tid < 32) g_coh[(size_t)pair * NN + t0 + tid] = scoh[tid];
}

// ---------------------------------------------------------------------------
// K3: sliding-window sum (window 94) -> out [64, 1955]. grid = 64*8 tiles
// ---------------------------------------------------------------------------
__global__ void __launch_bounds__(TPB) k3_window(float* __restrict__ out) {
    __shared__ float c[TPB + WSZ];
    int pair = blockIdx.x >> 3;
    int t0 = (blockIdx.x & 7) * TPB;
    int tid = threadIdx.x;
    for (int i = tid; i < TPB + WSZ; i += TPB) {
        int g = t0 + i;
        c[i] = (g < NN) ? g_coh[(size_t)pair * NN + g] : 0.f;
    }
    __syncthreads();
    int t = t0 + tid;
    if (t < NOUT) {
        float s = 0.f;
        #pragma unroll
        for (int k = 0; k < WSZ; k++) s += c[tid + k];
        out[(size_t)pair * NOUT + t] = s;
    }
}

// ---------------------------------------------------------------------------
// Entry point
// ---------------------------------------------------------------------------
extern "C" void kernel_launch(void* const* d_in, const int* in_sizes, int n_in,
                              void* d_out, int out_size) {
    (void)in_sizes; (void)n_in; (void)out_size;
    const float* x = (const float*)d_in[0];
    float* out = (float*)d_out;

    k0_normfft<<<NB * 2, TPB>>>(x);
    k1_scale<<<NB * NSC, TPB>>>();
    k2_coh<<<NB * 64, TPB>>>();
    k3_window<<<NB * 8, TPB>>>(out);
}

// round 11
// speedup vs baseline: 2.0002x; 1.0878x over previous
#include <cuda_runtime.h>
#include <cuda_fp16.h>

// ---------------------------------------------------------------------------
// Problem constants
// ---------------------------------------------------------------------------
#define NN     2048
#define NSC    81
#define NB     64
#define TPB    256
#define WSZ    94
#define NOUT   (NN - WSZ + 1)  // 1955

#define S0F        0.1936026618f            // 2*dt*(w0+sqrt(2+w0^2))/(4*pi)
#define WFAC       0.030679615757712823f    // 2*pi / (2048*0.1)
#define KFAC       0.0030679615757712823f   // 2*pi / 2048
#define TWOPI_F    6.283185307179586f
#define INV_PI4    0.7511255444649425f      // pi^(-1/4)
#define RSQ2       0.70710678118654752f
#define LAMB       16.0f                    // fp16 range centering; cancels in ratio

// ---------------------------------------------------------------------------
// Packed complex type: one 64-bit reg pair holding (re, im) as f32x2
// ---------------------------------------------------------------------------
typedef unsigned long long c64;

__device__ __forceinline__ c64 PKc(float x, float y) {
    c64 r; asm("mov.b64 %0, {%1,%2};" : "=l"(r) : "f"(x), "f"(y)); return r;
}
__device__ __forceinline__ void UPKc(c64 v, float& x, float& y) {
    asm("mov.b64 {%0,%1}, %2;" : "=f"(x), "=f"(y) : "l"(v));
}
__device__ __forceinline__ c64 padd(c64 a, c64 b) {
    c64 r; asm("add.rn.f32x2 %0, %1, %2;" : "=l"(r) : "l"(a), "l"(b)); return r;
}
__device__ __forceinline__ c64 pmul(c64 a, c64 b) {
    c64 r; asm("mul.rn.f32x2 %0, %1, %2;" : "=l"(r) : "l"(a), "l"(b)); return r;
}
__device__ __forceinline__ c64 pfma(c64 a, c64 b, c64 c) {
    c64 r; asm("fma.rn.f32x2 %0, %1, %2, %3;" : "=l"(r) : "l"(a), "l"(b), "l"(c)); return r;
}
__device__ __forceinline__ c64 psub(c64 a, c64 b) { return pfma(b, PKc(-1.f, -1.f), a); }
__device__ __forceinline__ c64 pswap(c64 v) { float x, y; UPKc(v, x, y); return PKc(y, x); }

// a*b (4 fp instrs)
__device__ __forceinline__ c64 cmulc(c64 a, c64 b) {
    float ax, ay, bx, by; UPKc(a, ax, ay); UPKc(b, bx, by);
    return PKc(fmaf(ax, bx, -ay * by), fmaf(ax, by, ay * bx));
}
// a*conj(b) (4 fp instrs) — used to apply inverse twiddles without negation
__device__ __forceinline__ c64 cmulcj(c64 a, c64 b) {
    float ax, ay, bx, by; UPKc(a, ax, ay); UPKc(b, bx, by);
    return PKc(fmaf(ax, bx, ay * by), fmaf(ay, bx, -ax * by));
}
template <bool INV>
__device__ __forceinline__ c64 capply(c64 a, c64 w) {
    return INV ? cmulcj(a, w) : cmulc(a, w);
}

// ---------------------------------------------------------------------------
// Scratch (device globals; no allocation anywhere)
// ---------------------------------------------------------------------------
static __device__ c64     g_Y [NB * 2 * NN];
static __device__ __half2 g_Tp[(size_t)NB * NSC * NN];  // (T1, T2) fp16 pair
static __device__ __half2 g_Tc[(size_t)NB * NSC * NN];  // (T12.re, T12.im) fp16 pair
static __device__ float   g_coh[NB * NN];

// ---------------------------------------------------------------------------
// Data-buffer bank swizzle (conflict-free for all FFT patterns below)
// ---------------------------------------------------------------------------
__device__ __forceinline__ int gmask(int h) { return (h & 7) ^ ((h & 4) << 1); }
__device__ __forceinline__ int sw(int i)    { return i ^ gmask(i >> 4); }

// ---------------------------------------------------------------------------
// Twiddle tables (forward sign; INV uses a*conj(w)):
//   tw[k]           = exp(-i*pi*k/1024), k in [0,512)   (pass4 w1, linear reads)
//   ptw2[m*8+p]     = exp(-i*pi*m*p/32),  m in [0,8), p in [0,8)
//   ptw3[(m-1)*64+p]= exp(-i*pi*m*p/256), m in [1,8), p in [0,64)
// ---------------------------------------------------------------------------
__device__ __forceinline__ void fill_tables(c64* tw, c64* ptw2, c64* ptw3, int t) {
    #pragma unroll
    for (int k = t; k < 512; k += TPB) {
        float s, c;
        sincospif(-(float)k * (1.0f / 1024.0f), &s, &c);
        tw[k] = PKc(c, s);
    }
    if (t < 64) {
        int m = t >> 3, p = t & 7;
        float s, c;
        sincospif(-(float)(m * p) * (1.0f / 32.0f), &s, &c);
        ptw2[t] = PKc(c, s);
    }
    #pragma unroll
    for (int k = t; k < 448; k += TPB) {
        int m = 1 + (k >> 6), p = k & 63;
        float s, c;
        sincospif(-(float)(m * p) * (1.0f / 256.0f), &s, &c);
        ptw3[k] = PKc(c, s);
    }
}

// ---------------------------------------------------------------------------
// Packed radix-8 butterflies
// ---------------------------------------------------------------------------
template <bool INV>
__device__ __forceinline__ void bf8_tail(c64 E0, c64 E1, c64 E2, c64 E3,
                                         c64 O0, c64 O1, c64 O2, c64 O3,
                                         c64 v[8]) {
    const c64 CI1 = INV ? PKc(-1.f, 1.f) : PKc(1.f, -1.f);
    const c64 CI2 = INV ? PKc(1.f, -1.f) : PKc(-1.f, 1.f);
    const c64 PIM = PKc(-1.f, 1.f);
    c64 q1 = pfma(pswap(O1), PIM, O1);
    c64 q3 = pfma(pswap(O3), PIM, O3);
    c64 W1 = INV ? pmul(q1, PKc(RSQ2, RSQ2))
                 : pmul(pswap(q1), PKc(RSQ2, -RSQ2));
    c64 W3 = INV ? pmul(pswap(q3), PKc(-RSQ2, RSQ2))
                 : pmul(q3, PKc(-RSQ2, -RSQ2));
    c64 O2s = pswap(O2);
    v[0] = padd(E0, O0);        v[4] = psub(E0, O0);
    v[1] = padd(E1, W1);        v[5] = psub(E1, W1);
    v[2] = pfma(O2s, CI1, E2);  v[6] = pfma(O2s, CI2, E2);
    v[3] = padd(E3, W3);        v[7] = psub(E3, W3);
}

template <bool INV>
__device__ __forceinline__ void bf8(c64 v[8]) {
    const c64 CI1 = INV ? PKc(-1.f, 1.f) : PKc(1.f, -1.f);
    const c64 CI2 = INV ? PKc(1.f, -1.f) : PKc(-1.f, 1.f);
    c64 e0 = padd(v[0], v[4]), e1 = psub(v[0], v[4]);
    c64 e2 = padd(v[2], v[6]), e3 = psub(v[2], v[6]);
    c64 e3s = pswap(e3);
    c64 E0 = padd(e0, e2), E2 = psub(e0, e2);
    c64 E1 = pfma(e3s, CI1, e1), E3 = pfma(e3s, CI2, e1);
    c64 o0 = padd(v[1], v[5]), o1 = psub(v[1], v[5]);
    c64 o2 = padd(v[3], v[7]), o3 = psub(v[3], v[7]);
    c64 o3s = pswap(o3);
    c64 O0 = padd(o0, o2), O2 = psub(o0, o2);
    c64 O1 = pfma(o3s, CI1, o1), O3 = pfma(o3s, CI2, o1);
    bf8_tail<INV>(E0, E1, E2, E3, O0, O1, O2, O3, v);
}

// Half-input butterfly: v[0..3] valid, v[4..7] == 0 (Morlet filter support)
template <bool INV>
__device__ __forceinline__ void bf8h(c64 v[8]) {
    const c64 CI1 = INV ? PKc(-1.f, 1.f) : PKc(1.f, -1.f);
    const c64 CI2 = INV ? PKc(1.f, -1.f) : PKc(-1.f, 1.f);
    c64 a0 = v[0], a1 = v[2], b0 = v[1], b1 = v[3];
    c64 a1s = pswap(a1);
    c64 E0 = padd(a0, a1), E2 = psub(a0, a1);
    c64 E1 = pfma(a1s, CI1, a0), E3 = pfma(a1s, CI2, a0);
    c64 b1s = pswap(b1);
    c64 O0 = padd(b0, b1), O2 = psub(b0, b1);
    c64 O1 = pfma(b1s, CI1, b0), O3 = pfma(b1s, CI2, b0);
    bf8_tail<INV>(E0, E1, E2, E3, O0, O1, O2, O3, v);
}

// ---------------------------------------------------------------------------
// Stockham passes, N = 2048 = 8*8*8*4, 256 threads, in-place swizzled buffer.
// Thread t's register set v[m] maps to logical positions t + 256*m at FFT
// boundaries — pass4_regs feeds pass1 / elementwise ops directly.
// ---------------------------------------------------------------------------
template <bool INV, bool HALF>
__device__ __forceinline__ void pass1(c64* A, c64 v[8], int t) {
    __syncthreads();           // prior readers of A are done
    if (HALF) bf8h<INV>(v); else bf8<INV>(v);
    int mw = gmask(t >> 1);
    int b8 = 8 * t;
    #pragma unroll
    for (int r = 0; r < 8; r++) A[(b8 + r) ^ mw] = v[r];
    __syncthreads();
}

template <bool INV>
__device__ __forceinline__ void pass2(c64* A, const c64* ptw2, int t) {
    c64 v[8];
    int mr = gmask(t >> 4);
    #pragma unroll
    for (int m = 0; m < 8; m++) v[m] = A[(t + 256 * m) ^ mr];
    int p = t & 7;
    #pragma unroll
    for (int m = 1; m < 8; m++) v[m] = capply<INV>(v[m], ptw2[m * 8 + p]);
    __syncthreads();
    bf8<INV>(v);
    int o = (t >> 3) * 64 + p;
    #pragma unroll
    for (int r = 0; r < 8; r++) { int i = o + 8 * r; A[sw(i)] = v[r]; }
    __syncthreads();
}

template <bool INV>
__device__ __forceinline__ void pass3(c64* A, const c64* ptw3, int t) {
    c64 v[8];
    int mr = gmask(t >> 4);
    #pragma unroll
    for (int m = 0; m < 8; m++) v[m] = A[(t + 256 * m) ^ mr];
    int p = t & 63;
    #pragma unroll
    for (int m = 1; m < 8; m++) v[m] = capply<INV>(v[m], ptw3[(m - 1) * 64 + p]);
    __syncthreads();
    bf8<INV>(v);
    int o = (t >> 6) * 512 + p;
    #pragma unroll
    for (int r = 0; r < 8; r++) { int i = o + 64 * r; A[sw(i)] = v[r]; }
    __syncthreads();
}

// Final radix-4 pass (NSv=512): RESULT IN REGISTERS, v[m] <-> position t+256m.
// j = t + 256b < 512, so tw[] needs only 512 entries; linear lane-consecutive reads.
template <bool INV>
__device__ __forceinline__ void pass4_regs(const c64* A, const c64* tw, int t, c64 v[8]) {
    const c64 CI1 = INV ? PKc(-1.f, 1.f) : PKc(1.f, -1.f);
    const c64 CI2 = INV ? PKc(1.f, -1.f) : PKc(-1.f, 1.f);
    #pragma unroll
    for (int b = 0; b < 2; b++) {
        int j = t + 256 * b;
        int mr = gmask(j >> 4);
        c64 v0 = A[j ^ mr];
        c64 v1 = A[(j + 512) ^ mr];
        c64 v2 = A[(j + 1024) ^ mr];
        c64 v3 = A[(j + 1536) ^ mr];
        c64 w1 = tw[j];
        c64 w2 = cmulc(w1, w1), w3 = cmulc(w2, w1);
        v1 = capply<INV>(v1, w1);
        v2 = capply<INV>(v2, w2);
        v3 = capply<INV>(v3, w3);
        c64 aa = padd(v0, v2), bb = psub(v0, v2);
        c64 cc = padd(v1, v3), dd = psub(v1, v3);
        c64 ds = pswap(dd);
        v[b + 0] = padd(aa, cc);       v[b + 4] = psub(aa, cc);
        v[b + 2] = pfma(ds, CI1, bb);  v[b + 6] = pfma(ds, CI2, bb);
    }
}

// Final pass for k0: store to smem (swizzled) so block can copy to global.
template <bool INV>
__device__ __forceinline__ void pass4(c64* A, const c64* tw, int t) {
    c64 v[8];
    pass4_regs<INV>(A, tw, t, v);
    __syncthreads();
    int mr = gmask(t >> 4);
    #pragma unroll
    for (int m = 0; m < 8; m++) A[(t + 256 * m) ^ mr] = v[m];
    __syncthreads();
}

// ---------------------------------------------------------------------------
// Block reduction (256 threads)
// ---------------------------------------------------------------------------
__device__ __forceinline__ float block_reduce(float v, float* red) {
    int tid = threadIdx.x;
    #pragma unroll
    for (int o = 16; o > 0; o >>= 1) v += __shfl_xor_sync(0xffffffffu, v, o);
    if ((tid & 31) == 0) red[tid >> 5] = v;
    __syncthreads();
    if (tid < 32) {
        float r = (tid < TPB / 32) ? red[tid] : 0.f;
        #pragma unroll
        for (int o = 4; o > 0; o >>= 1) r += __shfl_xor_sync(0xffffffffu, r, o);
        if (tid == 0) red[32] = r;
    }
    __syncthreads();
    float r = red[32];
    __syncthreads();
    return r;
}

// ---------------------------------------------------------------------------
// K0: normalize each signal + forward FFT -> g_Y.  grid = 128
// ---------------------------------------------------------------------------
__global__ void __launch_bounds__(TPB) k0_normfft(const float* __restrict__ x) {
    __shared__ c64 A[NN];
    __shared__ c64 tw[512];
    __shared__ c64 ptw2[64];
    __shared__ c64 ptw3[448];
    __shared__ float red[33];
    int b = blockIdx.x, t = threadIdx.x;
    const float* y = x + (size_t)b * NN;

    fill_tables(tw, ptw2, ptw3, t);

    float s = 0.f;
    #pragma unroll
    for (int i = t; i < NN; i += TPB) s += y[i];
    float mean = block_reduce(s, red) * (1.0f / NN);

    float vv = 0.f;
    #pragma unroll
    for (int i = t; i < NN; i += TPB) { float d = y[i] - mean; vv += d * d; }
    float istd = rsqrtf(block_reduce(vv, red) * (1.0f / NN));

    c64 v[8];
    #pragma unroll
    for (int m = 0; m < 8; m++) {
        int i = t + 256 * m;
        v[m] = PKc((y[i] - mean) * istd, 0.f);
    }
    pass1<false, false>(A, v, t);
    pass2<false>(A, ptw2, t);
    pass3<false>(A, ptw3, t);
    pass4<false>(A, tw, t);

    int mr = gmask(t >> 4);
    c64* out = g_Y + (size_t)b * NN;
    #pragma unroll
    for (int m = 0; m < 8; m++) { int i = t + 256 * m; out[i] = A[i ^ mr]; }
}

// ---------------------------------------------------------------------------
// K1: per (pair, scale) full chain; FFT junctions chained in registers;
// outputs stored as fp16 pairs. grid = 5184
// ---------------------------------------------------------------------------
__global__ void __launch_bounds__(TPB, 4) k1_scale() {
    __shared__ c64 A[NN];
    __shared__ c64 X[NN];      // stash: W1, then C (linear layout, conflict-free)
    __shared__ c64 tw[512];
    __shared__ c64 ptw2[64];
    __shared__ c64 ptw3[448];
    int blk = blockIdx.x;
    int pair = blk / NSC;
    int js = blk - pair * NSC;
    int t = threadIdx.x;

    fill_tables(tw, ptw2, ptw3, t);

    float sc  = S0F * exp2f(0.125f * (float)js);
    float nrm = sqrtf(TWOPI_F * sc * 10.0f) * INV_PI4;
    const c64* Y1 = g_Y + (size_t)pair * 2 * NN;
    const c64* Y2 = Y1 + NN;

    c64 v[8];

    // Morlet filter values for this thread's 4 low-half bins (reused for both CWTs)
    float hh[4];
    #pragma unroll
    for (int m = 0; m < 4; m++) {
        int i = t + 256 * m;
        float tt = sc * (WFAC * (float)i) - 6.0f;
        hh[m] = (i >= 1) ? nrm * __expf(-0.5f * tt * tt) : 0.f;
    }

    // ---- FFT1: W1 = unscaled ifft(Y1*H) -> stash to X ----
    #pragma unroll
    for (int m = 0; m < 4; m++) v[m] = pmul(Y1[t + 256 * m], PKc(hh[m], hh[m]));
    pass1<true, true>(A, v, t);
    pass2<true>(A, ptw2, t);
    pass3<true>(A, ptw3, t);
    pass4_regs<true>(A, tw, t, v);
    #pragma unroll
    for (int m = 0; m < 8; m++) X[t + 256 * m] = v[m];   // same-thread stash

    // ---- FFT2: W2 (in registers at the end) ----
    #pragma unroll
    for (int m = 0; m < 4; m++) v[m] = pmul(Y2[t + 256 * m], PKc(hh[m], hh[m]));
    pass1<true, true>(A, v, t);
    pass2<true>(A, ptw2, t);
    pass3<true>(A, ptw3, t);
    pass4_regs<true>(A, tw, t, v);                        // v = W2

    // ---- pointwise: pv = (|W1|^2 + i|W2|^2)*scf -> regs;  C = W1*conj(W2)*scf -> X
    const float scf = (LAMB / sc) * (1.0f / ((float)NN * (float)NN));
    #pragma unroll
    for (int m = 0; m < 8; m++) {
        float w1x, w1y, w2x, w2y;
        UPKc(X[t + 256 * m], w1x, w1y);                   // same-thread reload
        UPKc(v[m], w2x, w2y);
        X[t + 256 * m] = PKc((w1x * w2x + w1y * w2y) * scf,
                             (w1y * w2x - w1x * w2y) * scf);
        v[m] = PKc((w1x * w1x + w1y * w1y) * scf,
                   (w2x * w2x + w2y * w2y) * scf);
    }

    // ---- FFT3: forward fft of packed P (register input) ----
    pass1<false, false>(A, v, t);
    pass2<false>(A, ptw2, t);
    pass3<false>(A, ptw3, t);
    pass4_regs<false>(A, tw, t, v);

    // ---- Gaussian smoother in registers ----
    float sd = sc * 10.0f;
    float a2 = sd * sd;
    const float invN = 1.0f / (float)NN;
    #pragma unroll
    for (int m = 0; m < 8; m++) {
        int i = t + 256 * m;
        int f = (i < 1024) ? i : (NN - i);
        float k = KFAC * (float)f;
        float g = __expf(-0.5f * a2 * k * k) * invN;
        v[m] = pmul(v[m], PKc(g, g));
    }

    // ---- FFT4: inverse fft, write (T1,T2) as fp16 pairs to global ----
    size_t base = ((size_t)pair * NSC + js) * NN;
    pass1<true, false>(A, v, t);
    pass2<true>(A, ptw2, t);
    pass3<true>(A, ptw3, t);
    {
        c64 u[8];
        pass4_regs<true>(A, tw, t, u);
        __half2* Tp = g_Tp + base;
        #pragma unroll
        for (int m = 0; m < 8; m++) {
            float xx, yy; UPKc(u[m], xx, yy);
            Tp[t + 256 * m] = __floats2half2_rn(xx, yy);
        }
    }

    // ---- FFT5: forward fft of C (same-thread reload from X) ----
    #pragma unroll
    for (int m = 0; m < 8; m++) v[m] = X[t + 256 * m];
    pass1<false, false>(A, v, t);
    pass2<false>(A, ptw2, t);
    pass3<false>(A, ptw3, t);
    pass4_regs<false>(A, tw, t, v);

    // ---- Gaussian + FFT6: inverse fft, write T12 as fp16 pairs ----
    #pragma unroll
    for (int m = 0; m < 8; m++) {
        int i = t + 256 * m;
        int f = (i < 1024) ? i : (NN - i);
        float k = KFAC * (float)f;
        float g = __expf(-0.5f * a2 * k * k) * invN;
        v[m] = pmul(v[m], PKc(g, g));
    }
    pass1<true, false>(A, v, t);
    pass2<true>(A, ptw2, t);
    pass3<true>(A, ptw3, t);
    {
        c64 u[8];
        pass4_regs<true>(A, tw, t, u);
        __half2* Tc = g_Tc + base;
        #pragma unroll
        for (int m = 0; m < 8; m++) {
            float xx, yy; UPKc(u[m], xx, yy);
            Tc[t + 256 * m] = __floats2half2_rn(xx, yy);
        }
    }
}

// ---------------------------------------------------------------------------
// K2: scale smoothing (10-tap, half ends) + coherence + sum over scales.
// 1/9 window norm and LAMB cancel in the ratio. grid = 64*64
// ---------------------------------------------------------------------------
__global__ void __launch_bounds__(TPB) k2_coh() {
    __shared__ float s1[NSC * 32], s2[NSC * 32], cr[NSC * 32], ci[NSC * 32];
    __shared__ float scoh[32];
    int blk = blockIdx.x;
    int pair = blk >> 6;
    int t0 = (blk & 63) * 32;
    int tid = threadIdx.x;

    size_t base = (size_t)pair * NSC * NN + t0;
    for (int idx = tid; idx < NSC * 32; idx += TPB) {
        int row = idx >> 5, col = idx & 31;
        size_t g = base + (size_t)row * NN + col;
        float2 p = __half22float2(g_Tp[g]);
        float2 c = __half22float2(g_Tc[g]);
        s1[idx] = p.x;
        s2[idx] = p.y;
        cr[idx] = c.x;
        ci[idx] = c.y;
    }
    if (tid < 32) scoh[tid] = 0.f;
    __syncthreads();

    int tl = tid & 31, jg = tid >> 5;
    float acc = 0.f;
    for (int j = jg; j < NSC; j += 8) {
        float a = 0.f, b = 0.f, c = 0.f, d = 0.f;
        #pragma unroll
        for (int k = 0; k < 10; k++) {
            int r = j + 4 - k;
            if (r >= 0 && r < NSC) {
                float w = (k == 0 || k == 9) ? 0.5f : 1.0f;
                int ix = r * 32 + tl;
                a += w * s1[ix];
                b += w * s2[ix];
                c += w * cr[ix];
                d += w * ci[ix];
            }
        }
        acc += (c * c + d * d) / (a * b);
    }
    atomicAdd(&scoh[tl], acc);
    __syncthreads();
    if (tid < 32) g_coh[(size_t)pair * NN + t0 + tid] = scoh[tid];
}

// ---------------------------------------------------------------------------
// K3: sliding-window sum (window 94) -> out [64, 1955]. grid = 64*8 tiles
// ---------------------------------------------------------------------------
__global__ void __launch_bounds__(TPB) k3_window(float* __restrict__ out) {
    __shared__ float c[TPB + WSZ];
    int pair = blockIdx.x >> 3;
    int t0 = (blockIdx.x & 7) * TPB;
    int tid = threadIdx.x;
    for (int i = tid; i < TPB + WSZ; i += TPB) {
        int g = t0 + i;
        c[i] = (g < NN) ? g_coh[(size_t)pair * NN + g] : 0.f;
    }
    __syncthreads();
    int t = t0 + tid;
    if (t < NOUT) {
        float s = 0.f;
        #pragma unroll
        for (int k = 0; k < WSZ; k++) s += c[tid + k];
        out[(size_t)pair * NOUT + t] = s;
    }
}

// ---------------------------------------------------------------------------
// Entry point
// ---------------------------------------------------------------------------
extern "C" void kernel_launch(void* const* d_in, const int* in_sizes, int n_in,
                              void* d_out, int out_size) {
    (void)in_sizes; (void)n_in; (void)out_size;
    const float* x = (const float*)d_in[0];
    float* out = (float*)d_out;

    k0_normfft<<<NB * 2, TPB>>>(x);
    k1_scale<<<NB * NSC, TPB>>>();
    k2_coh<<<NB * 64, TPB>>>();
    k3_window<<<NB * 8, TPB>>>(out);
}